// round 2
// baseline (speedup 1.0000x reference)
#include <cuda_runtime.h>
#include <math.h>

#define BB   2
#define SS   2048
#define DD   1024
#define HH   16
#define DKH  64
#define DFF  4096
#define MM   (BB*SS)     // 4096 rows total
#define EPSV 1e-5f

// ---------------- scratch (device globals: allocation-free) ----------------
__device__ float g_xn [MM*DD];
__device__ float g_q  [MM*DD];
__device__ float g_k  [MM*DD];
__device__ float g_v  [MM*DD];
__device__ float g_att[MM*DD];
__device__ float g_x1 [MM*DD];
__device__ float g_xn2[MM*DD];
__device__ float g_ff [MM*DFF];

// ---------------- RMSNorm ----------------
__global__ void rmsnorm_kernel(const float* __restrict__ x,
                               const float* __restrict__ g,
                               float* __restrict__ out) {
    int row = blockIdx.x;
    int t = threadIdx.x; // 256 threads, 4 floats each = 1024
    float4 v = ((const float4*)(x + (size_t)row * DD))[t];
    float s = v.x*v.x + v.y*v.y + v.z*v.z + v.w*v.w;
    #pragma unroll
    for (int o = 16; o; o >>= 1) s += __shfl_xor_sync(0xffffffffu, s, o);
    __shared__ float ws[8];
    __shared__ float tot;
    if ((t & 31) == 0) ws[t >> 5] = s;
    __syncthreads();
    if (t == 0) {
        float z = 0.f;
        #pragma unroll
        for (int i = 0; i < 8; i++) z += ws[i];
        tot = rsqrtf(z * (1.0f / DD) + EPSV);
    }
    __syncthreads();
    float rn = tot;
    float4 gv = ((const float4*)g)[t];
    float4 ov = make_float4(v.x*rn*gv.x, v.y*rn*gv.y, v.z*rn*gv.z, v.w*rn*gv.w);
    ((float4*)(out + (size_t)row * DD))[t] = ov;
}

// ---------------- SGEMM: C[M,N] = A[M,K] * B[N,K]^T (+epilogue) ----------------
// EPI: 0 = none, 1 = +R (residual), 2 = gelu_erf
__device__ __forceinline__ float gelu_erf(float x) {
    return 0.5f * x * (1.0f + erff(x * 0.70710678118654752f));
}

template<int EPI>
__global__ void __launch_bounds__(256, 2)
gemm_kernel(const float* __restrict__ A, const float* __restrict__ B,
            const float* __restrict__ R, float* __restrict__ C,
            int M, int N, int K) {
    __shared__ float As[8][132];
    __shared__ float Bs[8][132];
    int tid = threadIdx.x;
    int bm = blockIdx.y * 128, bn = blockIdx.x * 128;
    int lr = tid >> 1;
    int lc = (tid & 1) * 4;
    const float* Ap = A + (size_t)(bm + lr) * K + lc;
    const float* Bp = B + (size_t)(bn + lr) * K + lc;
    int tx = tid & 15, ty = tid >> 4;

    float acc[8][8];
    #pragma unroll
    for (int i = 0; i < 8; i++)
        #pragma unroll
        for (int j = 0; j < 8; j++) acc[i][j] = 0.f;

    for (int k0 = 0; k0 < K; k0 += 8) {
        float4 a = *(const float4*)(Ap + k0);
        float4 b = *(const float4*)(Bp + k0);
        __syncthreads();
        As[lc+0][lr]=a.x; As[lc+1][lr]=a.y; As[lc+2][lr]=a.z; As[lc+3][lr]=a.w;
        Bs[lc+0][lr]=b.x; Bs[lc+1][lr]=b.y; Bs[lc+2][lr]=b.z; Bs[lc+3][lr]=b.w;
        __syncthreads();
        #pragma unroll
        for (int kk = 0; kk < 8; kk++) {
            float ar[8], br[8];
            *(float4*)(ar)   = *(const float4*)(&As[kk][ty*8]);
            *(float4*)(ar+4) = *(const float4*)(&As[kk][ty*8+4]);
            *(float4*)(br)   = *(const float4*)(&Bs[kk][tx*8]);
            *(float4*)(br+4) = *(const float4*)(&Bs[kk][tx*8+4]);
            #pragma unroll
            for (int i = 0; i < 8; i++)
                #pragma unroll
                for (int j = 0; j < 8; j++)
                    acc[i][j] = fmaf(ar[i], br[j], acc[i][j]);
        }
    }

    #pragma unroll
    for (int i = 0; i < 8; i++) {
        int r = bm + ty*8 + i;
        #pragma unroll
        for (int j = 0; j < 8; j += 4) {
            int c = bn + tx*8 + j;
            float4 o = make_float4(acc[i][j], acc[i][j+1], acc[i][j+2], acc[i][j+3]);
            if (EPI == 1) {
                float4 rv = *(const float4*)(R + (size_t)r * N + c);
                o.x += rv.x; o.y += rv.y; o.z += rv.z; o.w += rv.w;
            }
            if (EPI == 2) {
                o.x = gelu_erf(o.x); o.y = gelu_erf(o.y);
                o.z = gelu_erf(o.z); o.w = gelu_erf(o.w);
            }
            *(float4*)(C + (size_t)r * N + c) = o;
        }
    }
}

// ---------------- Flash attention (fp32, causal, dk=64) ----------------
// Block: 64 q-rows of one (b,h). 256 threads = 16x16, 4x4 micro-tile.
// Smem (dynamic, 69632 B): Qt[d][row], Kt[d][kv], Vs[kv][d], Ps[kv][row], pitch 68.
#define FP 68

__global__ void __launch_bounds__(256)
flash_kernel(const float* __restrict__ q, const float* __restrict__ k,
             const float* __restrict__ v, float* __restrict__ o) {
    extern __shared__ float sm[];
    float (*Qt)[FP] = (float(*)[FP])(sm);
    float (*Kt)[FP] = (float(*)[FP])(sm + 64*FP);
    float (*Vs)[FP] = (float(*)[FP])(sm + 2*64*FP);
    float (*Ps)[FP] = (float(*)[FP])(sm + 3*64*FP);

    int qi = blockIdx.x;           // q tile (0..31)
    int bh = blockIdx.y;           // b*H + h
    int b = bh >> 4, h = bh & 15;
    const float* qp    = q + ((size_t)(b*SS + qi*64)) * DD + h*DKH;
    const float* kbase = k + (size_t)b * SS * DD + h*DKH;
    const float* vbase = v + (size_t)b * SS * DD + h*DKH;

    int tid = threadIdx.x;
    int tx = tid & 15, ty = tid >> 4;
    int lrr = tid >> 2, lc4 = tid & 3;  // loader: row 0..63, col-chunk phase

    // Load Q tile transposed: Qt[d][row]
    #pragma unroll
    for (int cc = lc4; cc < 16; cc += 4) {
        float4 t4 = *(const float4*)(qp + (size_t)lrr * DD + cc*4);
        Qt[cc*4+0][lrr]=t4.x; Qt[cc*4+1][lrr]=t4.y;
        Qt[cc*4+2][lrr]=t4.z; Qt[cc*4+3][lrr]=t4.w;
    }

    float acc[4][4];
    float mrow[4], lrow[4];
    #pragma unroll
    for (int i = 0; i < 4; i++) {
        mrow[i] = -INFINITY; lrow[i] = 0.f;
        #pragma unroll
        for (int j = 0; j < 4; j++) acc[i][j] = 0.f;
    }

    for (int jt = 0; jt <= qi; jt++) {
        __syncthreads();  // prev PV done before overwriting Kt/Vs
        {
            const float* kp = kbase + (size_t)(jt*64 + lrr) * DD;
            const float* vp = vbase + (size_t)(jt*64 + lrr) * DD;
            #pragma unroll
            for (int cc = lc4; cc < 16; cc += 4) {
                float4 t4 = *(const float4*)(kp + cc*4);
                Kt[cc*4+0][lrr]=t4.x; Kt[cc*4+1][lrr]=t4.y;
                Kt[cc*4+2][lrr]=t4.z; Kt[cc*4+3][lrr]=t4.w;
                float4 u4 = *(const float4*)(vp + cc*4);
                *(float4*)(&Vs[lrr][cc*4]) = u4;
            }
        }
        __syncthreads();

        // S = Q K^T  (64x64 tile, each thread 4x4)
        float s[4][4];
        #pragma unroll
        for (int i = 0; i < 4; i++)
            #pragma unroll
            for (int j = 0; j < 4; j++) s[i][j] = 0.f;
        #pragma unroll 4
        for (int d = 0; d < 64; d++) {
            float4 qa = *(const float4*)(&Qt[d][ty*4]);
            float4 kb = *(const float4*)(&Kt[d][tx*4]);
            float qr[4] = {qa.x, qa.y, qa.z, qa.w};
            float kr[4] = {kb.x, kb.y, kb.z, kb.w};
            #pragma unroll
            for (int i = 0; i < 4; i++)
                #pragma unroll
                for (int j = 0; j < 4; j++)
                    s[i][j] = fmaf(qr[i], kr[j], s[i][j]);
        }

        bool diag = (jt == qi);
        #pragma unroll
        for (int i = 0; i < 4; i++)
            #pragma unroll
            for (int j = 0; j < 4; j++) {
                float val = s[i][j] * 0.125f;
                if (diag && (tx*4 + j > ty*4 + i)) val = -INFINITY;
                s[i][j] = val;
            }

        // row max over the 16-lane tx group
        float rm[4];
        #pragma unroll
        for (int i = 0; i < 4; i++)
            rm[i] = fmaxf(fmaxf(s[i][0], s[i][1]), fmaxf(s[i][2], s[i][3]));
        #pragma unroll
        for (int off = 8; off; off >>= 1)
            #pragma unroll
            for (int i = 0; i < 4; i++)
                rm[i] = fmaxf(rm[i], __shfl_xor_sync(0xffffffffu, rm[i], off, 16));

        float p[4][4], rs[4];
        #pragma unroll
        for (int i = 0; i < 4; i++) {
            float mnew = fmaxf(mrow[i], rm[i]);
            float corr = __expf(mrow[i] - mnew);
            mrow[i] = mnew;
            lrow[i] *= corr;
            rs[i] = 0.f;
            #pragma unroll
            for (int j = 0; j < 4; j++) {
                p[i][j] = __expf(s[i][j] - mnew);
                rs[i] += p[i][j];
                acc[i][j] *= corr;
            }
        }
        #pragma unroll
        for (int off = 8; off; off >>= 1)
            #pragma unroll
            for (int i = 0; i < 4; i++)
                rs[i] += __shfl_xor_sync(0xffffffffu, rs[i], off, 16);
        #pragma unroll
        for (int i = 0; i < 4; i++) lrow[i] += rs[i];

        // share P (transposed: Ps[kv][row])
        #pragma unroll
        for (int i = 0; i < 4; i++)
            #pragma unroll
            for (int j = 0; j < 4; j++)
                Ps[tx*4 + j][ty*4 + i] = p[i][j];
        __syncthreads();

        // O += P V
        #pragma unroll 4
        for (int jj = 0; jj < 64; jj++) {
            float4 pv = *(const float4*)(&Ps[jj][ty*4]);
            float4 vv = *(const float4*)(&Vs[jj][tx*4]);
            float pr[4] = {pv.x, pv.y, pv.z, pv.w};
            float vr[4] = {vv.x, vv.y, vv.z, vv.w};
            #pragma unroll
            for (int i = 0; i < 4; i++)
                #pragma unroll
                for (int j = 0; j < 4; j++)
                    acc[i][j] = fmaf(pr[i], vr[j], acc[i][j]);
        }
    }

    float* op = o + ((size_t)(b*SS + qi*64)) * DD + h*DKH;
    #pragma unroll
    for (int i = 0; i < 4; i++) {
        float inv = 1.0f / lrow[i];
        float4 o4 = make_float4(acc[i][0]*inv, acc[i][1]*inv, acc[i][2]*inv, acc[i][3]*inv);
        *(float4*)(op + (size_t)(ty*4 + i) * DD + tx*4) = o4;
    }
}

// ---------------- launch ----------------
extern "C" void kernel_launch(void* const* d_in, const int* in_sizes, int n_in,
                              void* d_out, int out_size) {
    const float* x  = (const float*)d_in[0];
    const float* g1 = (const float*)d_in[1];
    const float* g2 = (const float*)d_in[2];
    const float* wq = (const float*)d_in[3];
    const float* wk = (const float*)d_in[4];
    const float* wv = (const float*)d_in[5];
    const float* wo = (const float*)d_in[6];
    const float* w1 = (const float*)d_in[7];
    const float* w2 = (const float*)d_in[8];
    float* out = (float*)d_out;

    float *xn, *q, *k, *v, *att, *x1, *xn2, *ff;
    cudaGetSymbolAddress((void**)&xn,  g_xn);
    cudaGetSymbolAddress((void**)&q,   g_q);
    cudaGetSymbolAddress((void**)&k,   g_k);
    cudaGetSymbolAddress((void**)&v,   g_v);
    cudaGetSymbolAddress((void**)&att, g_att);
    cudaGetSymbolAddress((void**)&x1,  g_x1);
    cudaGetSymbolAddress((void**)&xn2, g_xn2);
    cudaGetSymbolAddress((void**)&ff,  g_ff);

    cudaFuncSetAttribute(flash_kernel,
                         cudaFuncAttributeMaxDynamicSharedMemorySize, 4*64*FP*4);

    dim3 gD(DD/128, MM/128);    // N=1024 GEMMs
    dim3 gF(DFF/128, MM/128);   // N=4096 GEMM

    // 1. xn = rmsnorm(x, g1)
    rmsnorm_kernel<<<MM, 256>>>(x, g1, xn);
    // 2. Q, K, V projections
    gemm_kernel<0><<<gD, 256>>>(xn, wq, nullptr, q, MM, DD, DD);
    gemm_kernel<0><<<gD, 256>>>(xn, wk, nullptr, k, MM, DD, DD);
    gemm_kernel<0><<<gD, 256>>>(xn, wv, nullptr, v, MM, DD, DD);
    // 3. causal flash attention
    flash_kernel<<<dim3(SS/64, BB*HH), 256, 4*64*FP*4>>>(q, k, v, att);
    // 4. x1 = x + att @ wo^T
    gemm_kernel<1><<<gD, 256>>>(att, wo, x, x1, MM, DD, DD);
    // 5. xn2 = rmsnorm(x1, g2)
    rmsnorm_kernel<<<MM, 256>>>(x1, g2, xn2);
    // 6. ff = gelu(xn2 @ w1^T)
    gemm_kernel<2><<<gF, 256>>>(xn2, w1, nullptr, ff, MM, DFF, DD);
    // 7. out = x1 + ff @ w2^T
    gemm_kernel<1><<<gD, 256>>>(ff, w2, x1, out, MM, DD, DFF);
}

// round 3
// speedup vs baseline: 2.0425x; 2.0425x over previous
#include <cuda_runtime.h>
#include <math.h>
#include <stdint.h>

#define BB   2
#define SS   2048
#define DD   1024
#define HH   16
#define DKH  64
#define DFF  4096
#define MM   (BB*SS)     // 4096 rows total
#define EPSV 1e-5f

// ---------------- scratch (device globals: allocation-free) ----------------
__device__ float g_xn [MM*DD];
__device__ float g_q  [MM*DD];
__device__ float g_k  [MM*DD];
__device__ float g_v  [MM*DD];
__device__ float g_att[MM*DD];
__device__ float g_x1 [MM*DD];
__device__ float g_xn2[MM*DD];
__device__ float g_ff [MM*DFF];

// ---------------- RMSNorm ----------------
__global__ void rmsnorm_kernel(const float* __restrict__ x,
                               const float* __restrict__ g,
                               float* __restrict__ out) {
    int row = blockIdx.x;
    int t = threadIdx.x; // 256 threads, 4 floats each = 1024
    float4 v = ((const float4*)(x + (size_t)row * DD))[t];
    float s = v.x*v.x + v.y*v.y + v.z*v.z + v.w*v.w;
    #pragma unroll
    for (int o = 16; o; o >>= 1) s += __shfl_xor_sync(0xffffffffu, s, o);
    __shared__ float ws[8];
    __shared__ float tot;
    if ((t & 31) == 0) ws[t >> 5] = s;
    __syncthreads();
    if (t == 0) {
        float z = 0.f;
        #pragma unroll
        for (int i = 0; i < 8; i++) z += ws[i];
        tot = rsqrtf(z * (1.0f / DD) + EPSV);
    }
    __syncthreads();
    float rn = tot;
    float4 gv = ((const float4*)g)[t];
    float4 ov = make_float4(v.x*rn*gv.x, v.y*rn*gv.y, v.z*rn*gv.z, v.w*rn*gv.w);
    ((float4*)(out + (size_t)row * DD))[t] = ov;
}

// ---------------- tf32 tensor-core GEMM: C[M,N] = A[M,K] * B[N,K]^T ----------------
__device__ __forceinline__ float gelu_erf(float x) {
    return 0.5f * x * (1.0f + erff(x * 0.70710678118654752f));
}
__device__ __forceinline__ float to_tf32(float x) {
    float r;
    asm("cvt.rna.tf32.f32 %0, %1;" : "=f"(r) : "f"(x));
    return r;
}
__device__ __forceinline__ float4 cvt4(float4 v) {
    return make_float4(to_tf32(v.x), to_tf32(v.y), to_tf32(v.z), to_tf32(v.w));
}
__device__ __forceinline__ void mma_tf32(float c[4],
                                         uint32_t a0, uint32_t a1, uint32_t a2, uint32_t a3,
                                         uint32_t b0, uint32_t b1) {
    asm volatile(
        "mma.sync.aligned.m16n8k8.row.col.f32.tf32.tf32.f32 "
        "{%0,%1,%2,%3},{%4,%5,%6,%7},{%8,%9},{%0,%1,%2,%3};"
        : "+f"(c[0]), "+f"(c[1]), "+f"(c[2]), "+f"(c[3])
        : "r"(a0), "r"(a1), "r"(a2), "r"(a3), "r"(b0), "r"(b1));
}

#define BKP 20   // smem pitch (words): conflict-free frag LDS, float4-aligned

// EPI: 0 = none, 1 = +R (residual), 2 = gelu_erf
template<int EPI>
__global__ void __launch_bounds__(256, 2)
gemm_tc(const float* __restrict__ A, const float* __restrict__ B,
        const float* __restrict__ R, float* __restrict__ C,
        int M, int N, int K) {
    __shared__ float As[128][BKP];
    __shared__ float Bs[128][BKP];
    int tid = threadIdx.x;
    int bm = blockIdx.y * 128, bn = blockIdx.x * 128;
    int wid = tid >> 5, lane = tid & 31;
    int warp_m = (wid & 1) * 64;      // 2 warps along M
    int warp_n = (wid >> 1) * 32;     // 4 warps along N
    int tg = lane >> 2, tq = lane & 3;

    // loader: thread -> (row 0..63, 16-float k-chunk col)
    int lrow = tid >> 2;
    int lc = (tid & 3) * 4;
    const float* Ap = A + (size_t)(bm + lrow) * K + lc;
    const float* Bp = B + (size_t)(bn + lrow) * K + lc;
    const size_t rstep = (size_t)64 * K;

    float acc[4][4][4];
    #pragma unroll
    for (int i = 0; i < 4; i++)
        #pragma unroll
        for (int j = 0; j < 4; j++)
            #pragma unroll
            for (int q = 0; q < 4; q++) acc[i][j][q] = 0.f;

    // prologue prefetch
    float4 pa0 = *(const float4*)(Ap);
    float4 pa1 = *(const float4*)(Ap + rstep);
    float4 pb0 = *(const float4*)(Bp);
    float4 pb1 = *(const float4*)(Bp + rstep);

    for (int k0 = 0; k0 < K; k0 += 16) {
        *(float4*)(&As[lrow][lc])      = cvt4(pa0);
        *(float4*)(&As[lrow + 64][lc]) = cvt4(pa1);
        *(float4*)(&Bs[lrow][lc])      = cvt4(pb0);
        *(float4*)(&Bs[lrow + 64][lc]) = cvt4(pb1);
        __syncthreads();
        if (k0 + 16 < K) {
            pa0 = *(const float4*)(Ap + k0 + 16);
            pa1 = *(const float4*)(Ap + rstep + k0 + 16);
            pb0 = *(const float4*)(Bp + k0 + 16);
            pb1 = *(const float4*)(Bp + rstep + k0 + 16);
        }
        #pragma unroll
        for (int kt = 0; kt < 2; kt++) {
            int kb = kt * 8;
            uint32_t af[4][4];
            #pragma unroll
            for (int mt = 0; mt < 4; mt++) {
                int r = warp_m + mt * 16;
                af[mt][0] = __float_as_uint(As[r + tg][kb + tq]);
                af[mt][1] = __float_as_uint(As[r + tg + 8][kb + tq]);
                af[mt][2] = __float_as_uint(As[r + tg][kb + tq + 4]);
                af[mt][3] = __float_as_uint(As[r + tg + 8][kb + tq + 4]);
            }
            uint32_t bf[4][2];
            #pragma unroll
            for (int nt = 0; nt < 4; nt++) {
                int c = warp_n + nt * 8;
                bf[nt][0] = __float_as_uint(Bs[c + tg][kb + tq]);
                bf[nt][1] = __float_as_uint(Bs[c + tg][kb + tq + 4]);
            }
            #pragma unroll
            for (int mt = 0; mt < 4; mt++)
                #pragma unroll
                for (int nt = 0; nt < 4; nt++)
                    mma_tf32(acc[mt][nt], af[mt][0], af[mt][1], af[mt][2], af[mt][3],
                             bf[nt][0], bf[nt][1]);
        }
        __syncthreads();
    }

    // epilogue
    #pragma unroll
    for (int mt = 0; mt < 4; mt++) {
        #pragma unroll
        for (int nt = 0; nt < 4; nt++) {
            int r0 = bm + warp_m + mt * 16 + tg;
            int r1 = r0 + 8;
            int c = bn + warp_n + nt * 8 + tq * 2;
            float2 v0 = make_float2(acc[mt][nt][0], acc[mt][nt][1]);
            float2 v1 = make_float2(acc[mt][nt][2], acc[mt][nt][3]);
            if (EPI == 1) {
                float2 rv0 = *(const float2*)(R + (size_t)r0 * N + c);
                float2 rv1 = *(const float2*)(R + (size_t)r1 * N + c);
                v0.x += rv0.x; v0.y += rv0.y;
                v1.x += rv1.x; v1.y += rv1.y;
            }
            if (EPI == 2) {
                v0.x = gelu_erf(v0.x); v0.y = gelu_erf(v0.y);
                v1.x = gelu_erf(v1.x); v1.y = gelu_erf(v1.y);
            }
            *(float2*)(C + (size_t)r0 * N + c) = v0;
            *(float2*)(C + (size_t)r1 * N + c) = v1;
        }
    }
}

// ---------------- Flash attention (fp32, causal, dk=64) ----------------
#define FP 68

__global__ void __launch_bounds__(256)
flash_kernel(const float* __restrict__ q, const float* __restrict__ k,
             const float* __restrict__ v, float* __restrict__ o) {
    extern __shared__ float sm[];
    float (*Qt)[FP] = (float(*)[FP])(sm);
    float (*Kt)[FP] = (float(*)[FP])(sm + 64*FP);
    float (*Vs)[FP] = (float(*)[FP])(sm + 2*64*FP);
    float (*Ps)[FP] = (float(*)[FP])(sm + 3*64*FP);

    int qi = blockIdx.x;           // q tile (0..31)
    int bh = blockIdx.y;           // b*H + h
    int b = bh >> 4, h = bh & 15;
    const float* qp    = q + ((size_t)(b*SS + qi*64)) * DD + h*DKH;
    const float* kbase = k + (size_t)b * SS * DD + h*DKH;
    const float* vbase = v + (size_t)b * SS * DD + h*DKH;

    int tid = threadIdx.x;
    int tx = tid & 15, ty = tid >> 4;
    int lrr = tid >> 2, lc4 = tid & 3;

    #pragma unroll
    for (int cc = lc4; cc < 16; cc += 4) {
        float4 t4 = *(const float4*)(qp + (size_t)lrr * DD + cc*4);
        Qt[cc*4+0][lrr]=t4.x; Qt[cc*4+1][lrr]=t4.y;
        Qt[cc*4+2][lrr]=t4.z; Qt[cc*4+3][lrr]=t4.w;
    }

    float acc[4][4];
    float mrow[4], lrow[4];
    #pragma unroll
    for (int i = 0; i < 4; i++) {
        mrow[i] = -INFINITY; lrow[i] = 0.f;
        #pragma unroll
        for (int j = 0; j < 4; j++) acc[i][j] = 0.f;
    }

    for (int jt = 0; jt <= qi; jt++) {
        __syncthreads();
        {
            const float* kp = kbase + (size_t)(jt*64 + lrr) * DD;
            const float* vp = vbase + (size_t)(jt*64 + lrr) * DD;
            #pragma unroll
            for (int cc = lc4; cc < 16; cc += 4) {
                float4 t4 = *(const float4*)(kp + cc*4);
                Kt[cc*4+0][lrr]=t4.x; Kt[cc*4+1][lrr]=t4.y;
                Kt[cc*4+2][lrr]=t4.z; Kt[cc*4+3][lrr]=t4.w;
                float4 u4 = *(const float4*)(vp + cc*4);
                *(float4*)(&Vs[lrr][cc*4]) = u4;
            }
        }
        __syncthreads();

        float s[4][4];
        #pragma unroll
        for (int i = 0; i < 4; i++)
            #pragma unroll
            for (int j = 0; j < 4; j++) s[i][j] = 0.f;
        #pragma unroll 4
        for (int d = 0; d < 64; d++) {
            float4 qa = *(const float4*)(&Qt[d][ty*4]);
            float4 kb = *(const float4*)(&Kt[d][tx*4]);
            float qr[4] = {qa.x, qa.y, qa.z, qa.w};
            float kr[4] = {kb.x, kb.y, kb.z, kb.w};
            #pragma unroll
            for (int i = 0; i < 4; i++)
                #pragma unroll
                for (int j = 0; j < 4; j++)
                    s[i][j] = fmaf(qr[i], kr[j], s[i][j]);
        }

        bool diag = (jt == qi);
        #pragma unroll
        for (int i = 0; i < 4; i++)
            #pragma unroll
            for (int j = 0; j < 4; j++) {
                float val = s[i][j] * 0.125f;
                if (diag && (tx*4 + j > ty*4 + i)) val = -INFINITY;
                s[i][j] = val;
            }

        float rm[4];
        #pragma unroll
        for (int i = 0; i < 4; i++)
            rm[i] = fmaxf(fmaxf(s[i][0], s[i][1]), fmaxf(s[i][2], s[i][3]));
        #pragma unroll
        for (int off = 8; off; off >>= 1)
            #pragma unroll
            for (int i = 0; i < 4; i++)
                rm[i] = fmaxf(rm[i], __shfl_xor_sync(0xffffffffu, rm[i], off, 16));

        float p[4][4], rs[4];
        #pragma unroll
        for (int i = 0; i < 4; i++) {
            float mnew = fmaxf(mrow[i], rm[i]);
            float corr = __expf(mrow[i] - mnew);
            mrow[i] = mnew;
            lrow[i] *= corr;
            rs[i] = 0.f;
            #pragma unroll
            for (int j = 0; j < 4; j++) {
                p[i][j] = __expf(s[i][j] - mnew);
                rs[i] += p[i][j];
                acc[i][j] *= corr;
            }
        }
        #pragma unroll
        for (int off = 8; off; off >>= 1)
            #pragma unroll
            for (int i = 0; i < 4; i++)
                rs[i] += __shfl_xor_sync(0xffffffffu, rs[i], off, 16);
        #pragma unroll
        for (int i = 0; i < 4; i++) lrow[i] += rs[i];

        #pragma unroll
        for (int i = 0; i < 4; i++)
            #pragma unroll
            for (int j = 0; j < 4; j++)
                Ps[tx*4 + j][ty*4 + i] = p[i][j];
        __syncthreads();

        #pragma unroll 4
        for (int jj = 0; jj < 64; jj++) {
            float4 pv = *(const float4*)(&Ps[jj][ty*4]);
            float4 vv = *(const float4*)(&Vs[jj][tx*4]);
            float pr[4] = {pv.x, pv.y, pv.z, pv.w};
            float vr[4] = {vv.x, vv.y, vv.z, vv.w};
            #pragma unroll
            for (int i = 0; i < 4; i++)
                #pragma unroll
                for (int j = 0; j < 4; j++)
                    acc[i][j] = fmaf(pr[i], vr[j], acc[i][j]);
        }
    }

    float* op = o + ((size_t)(b*SS + qi*64)) * DD + h*DKH;
    #pragma unroll
    for (int i = 0; i < 4; i++) {
        float inv = 1.0f / lrow[i];
        float4 o4 = make_float4(acc[i][0]*inv, acc[i][1]*inv, acc[i][2]*inv, acc[i][3]*inv);
        *(float4*)(op + (size_t)(ty*4 + i) * DD + tx*4) = o4;
    }
}

// ---------------- launch ----------------
extern "C" void kernel_launch(void* const* d_in, const int* in_sizes, int n_in,
                              void* d_out, int out_size) {
    const float* x  = (const float*)d_in[0];
    const float* g1 = (const float*)d_in[1];
    const float* g2 = (const float*)d_in[2];
    const float* wq = (const float*)d_in[3];
    const float* wk = (const float*)d_in[4];
    const float* wv = (const float*)d_in[5];
    const float* wo = (const float*)d_in[6];
    const float* w1 = (const float*)d_in[7];
    const float* w2 = (const float*)d_in[8];
    float* out = (float*)d_out;

    float *xn, *q, *k, *v, *att, *x1, *xn2, *ff;
    cudaGetSymbolAddress((void**)&xn,  g_xn);
    cudaGetSymbolAddress((void**)&q,   g_q);
    cudaGetSymbolAddress((void**)&k,   g_k);
    cudaGetSymbolAddress((void**)&v,   g_v);
    cudaGetSymbolAddress((void**)&att, g_att);
    cudaGetSymbolAddress((void**)&x1,  g_x1);
    cudaGetSymbolAddress((void**)&xn2, g_xn2);
    cudaGetSymbolAddress((void**)&ff,  g_ff);

    cudaFuncSetAttribute(flash_kernel,
                         cudaFuncAttributeMaxDynamicSharedMemorySize, 4*64*FP*4);

    dim3 gD(DD/128, MM/128);    // N=1024 GEMMs
    dim3 gF(DFF/128, MM/128);   // N=4096 GEMM

    // 1. xn = rmsnorm(x, g1)
    rmsnorm_kernel<<<MM, 256>>>(x, g1, xn);
    // 2. Q, K, V projections (tf32 tensor cores)
    gemm_tc<0><<<gD, 256>>>(xn, wq, nullptr, q, MM, DD, DD);
    gemm_tc<0><<<gD, 256>>>(xn, wk, nullptr, k, MM, DD, DD);
    gemm_tc<0><<<gD, 256>>>(xn, wv, nullptr, v, MM, DD, DD);
    // 3. causal flash attention
    flash_kernel<<<dim3(SS/64, BB*HH), 256, 4*64*FP*4>>>(q, k, v, att);
    // 4. x1 = x + att @ wo^T
    gemm_tc<1><<<gD, 256>>>(att, wo, x, x1, MM, DD, DD);
    // 5. xn2 = rmsnorm(x1, g2)
    rmsnorm_kernel<<<MM, 256>>>(x1, g2, xn2);
    // 6. ff = gelu(xn2 @ w1^T)
    gemm_tc<2><<<gF, 256>>>(xn2, w1, nullptr, ff, MM, DFF, DD);
    // 7. out = x1 + ff @ w2^T
    gemm_tc<1><<<gD, 256>>>(ff, w2, x1, out, MM, DD, DFF);
}

// round 4
// speedup vs baseline: 2.8596x; 1.4001x over previous
#include <cuda_runtime.h>
#include <math.h>
#include <stdint.h>

#define BB   2
#define SS   2048
#define DD   1024
#define HH   16
#define DKH  64
#define DFF  4096
#define MM   (BB*SS)     // 4096 rows total
#define EPSV 1e-5f

// ---------------- scratch (device globals: allocation-free) ----------------
__device__ float g_xn [MM*DD];
__device__ float g_q  [MM*DD];
__device__ float g_k  [MM*DD];
__device__ float g_v  [MM*DD];
__device__ float g_att[MM*DD];
__device__ float g_x1 [MM*DD];
__device__ float g_xn2[MM*DD];
__device__ float g_ff [MM*DFF];

// ---------------- RMSNorm ----------------
__global__ void rmsnorm_kernel(const float* __restrict__ x,
                               const float* __restrict__ g,
                               float* __restrict__ out) {
    int row = blockIdx.x;
    int t = threadIdx.x; // 256 threads, 4 floats each = 1024
    float4 v = ((const float4*)(x + (size_t)row * DD))[t];
    float s = v.x*v.x + v.y*v.y + v.z*v.z + v.w*v.w;
    #pragma unroll
    for (int o = 16; o; o >>= 1) s += __shfl_xor_sync(0xffffffffu, s, o);
    __shared__ float ws[8];
    __shared__ float tot;
    if ((t & 31) == 0) ws[t >> 5] = s;
    __syncthreads();
    if (t == 0) {
        float z = 0.f;
        #pragma unroll
        for (int i = 0; i < 8; i++) z += ws[i];
        tot = rsqrtf(z * (1.0f / DD) + EPSV);
    }
    __syncthreads();
    float rn = tot;
    float4 gv = ((const float4*)g)[t];
    float4 ov = make_float4(v.x*rn*gv.x, v.y*rn*gv.y, v.z*rn*gv.z, v.w*rn*gv.w);
    ((float4*)(out + (size_t)row * DD))[t] = ov;
}

// ---------------- helpers ----------------
__device__ __forceinline__ float gelu_erf(float x) {
    return 0.5f * x * (1.0f + erff(x * 0.70710678118654752f));
}
__device__ __forceinline__ float to_tf32(float x) {
    float r;
    asm("cvt.rna.tf32.f32 %0, %1;" : "=f"(r) : "f"(x));
    return r;
}
__device__ __forceinline__ float4 cvt4(float4 v) {
    return make_float4(to_tf32(v.x), to_tf32(v.y), to_tf32(v.z), to_tf32(v.w));
}
__device__ __forceinline__ void mma_tf32(float c[4],
                                         uint32_t a0, uint32_t a1, uint32_t a2, uint32_t a3,
                                         uint32_t b0, uint32_t b1) {
    asm volatile(
        "mma.sync.aligned.m16n8k8.row.col.f32.tf32.tf32.f32 "
        "{%0,%1,%2,%3},{%4,%5,%6,%7},{%8,%9},{%0,%1,%2,%3};"
        : "+f"(c[0]), "+f"(c[1]), "+f"(c[2]), "+f"(c[3])
        : "r"(a0), "r"(a1), "r"(a2), "r"(a3), "r"(b0), "r"(b1));
}

// ---------------- tf32 tensor-core GEMM: C = A[M,K] * B[N,K]^T (+epilogue) ----------------
#define BKP 20   // smem pitch (words)

// EPI: 0 = none, 1 = +R (residual), 2 = gelu_erf
template<int EPI>
__global__ void __launch_bounds__(256, 2)
gemm_tc(const float* __restrict__ A, const float* __restrict__ B,
        const float* __restrict__ R, float* __restrict__ C,
        int M, int N, int K) {
    __shared__ float As[2][128][BKP];
    __shared__ float Bs[2][128][BKP];
    int tid = threadIdx.x;
    int bm = blockIdx.y * 128, bn = blockIdx.x * 128;
    int wid = tid >> 5, lane = tid & 31;
    int warp_m = (wid & 1) * 64;      // 2 warps along M
    int warp_n = (wid >> 1) * 32;     // 4 warps along N
    int tg = lane >> 2, tq = lane & 3;

    int lrow = tid >> 2;
    int lc = (tid & 3) * 4;
    const float* Ap = A + (size_t)(bm + lrow) * K + lc;
    const float* Bp = B + (size_t)(bn + lrow) * K + lc;
    const size_t rstep = (size_t)64 * K;

    float acc[4][4][4];
    #pragma unroll
    for (int i = 0; i < 4; i++)
        #pragma unroll
        for (int j = 0; j < 4; j++)
            #pragma unroll
            for (int q = 0; q < 4; q++) acc[i][j][q] = 0.f;

    // prologue: tile 0
    {
        float4 pa0 = *(const float4*)(Ap);
        float4 pa1 = *(const float4*)(Ap + rstep);
        float4 pb0 = *(const float4*)(Bp);
        float4 pb1 = *(const float4*)(Bp + rstep);
        *(float4*)(&As[0][lrow][lc])      = cvt4(pa0);
        *(float4*)(&As[0][lrow + 64][lc]) = cvt4(pa1);
        *(float4*)(&Bs[0][lrow][lc])      = cvt4(pb0);
        *(float4*)(&Bs[0][lrow + 64][lc]) = cvt4(pb1);
    }
    __syncthreads();

    int cur = 0;
    for (int k0 = 0; k0 < K; k0 += 16) {
        bool more = (k0 + 16) < K;
        float4 pa0, pa1, pb0, pb1;
        if (more) {
            pa0 = *(const float4*)(Ap + k0 + 16);
            pa1 = *(const float4*)(Ap + rstep + k0 + 16);
            pb0 = *(const float4*)(Bp + k0 + 16);
            pb1 = *(const float4*)(Bp + rstep + k0 + 16);
        }
        #pragma unroll
        for (int kt = 0; kt < 2; kt++) {
            int kb = kt * 8;
            uint32_t af[4][4];
            #pragma unroll
            for (int mt = 0; mt < 4; mt++) {
                int r = warp_m + mt * 16;
                af[mt][0] = __float_as_uint(As[cur][r + tg][kb + tq]);
                af[mt][1] = __float_as_uint(As[cur][r + tg + 8][kb + tq]);
                af[mt][2] = __float_as_uint(As[cur][r + tg][kb + tq + 4]);
                af[mt][3] = __float_as_uint(As[cur][r + tg + 8][kb + tq + 4]);
            }
            uint32_t bf[4][2];
            #pragma unroll
            for (int nt = 0; nt < 4; nt++) {
                int c = warp_n + nt * 8;
                bf[nt][0] = __float_as_uint(Bs[cur][c + tg][kb + tq]);
                bf[nt][1] = __float_as_uint(Bs[cur][c + tg][kb + tq + 4]);
            }
            #pragma unroll
            for (int mt = 0; mt < 4; mt++)
                #pragma unroll
                for (int nt = 0; nt < 4; nt++)
                    mma_tf32(acc[mt][nt], af[mt][0], af[mt][1], af[mt][2], af[mt][3],
                             bf[nt][0], bf[nt][1]);
        }
        if (more) {
            int nxt = cur ^ 1;
            *(float4*)(&As[nxt][lrow][lc])      = cvt4(pa0);
            *(float4*)(&As[nxt][lrow + 64][lc]) = cvt4(pa1);
            *(float4*)(&Bs[nxt][lrow][lc])      = cvt4(pb0);
            *(float4*)(&Bs[nxt][lrow + 64][lc]) = cvt4(pb1);
        }
        __syncthreads();
        cur ^= 1;
    }

    // epilogue
    #pragma unroll
    for (int mt = 0; mt < 4; mt++) {
        #pragma unroll
        for (int nt = 0; nt < 4; nt++) {
            int r0 = bm + warp_m + mt * 16 + tg;
            int r1 = r0 + 8;
            int c = bn + warp_n + nt * 8 + tq * 2;
            float2 v0 = make_float2(acc[mt][nt][0], acc[mt][nt][1]);
            float2 v1 = make_float2(acc[mt][nt][2], acc[mt][nt][3]);
            if (EPI == 1) {
                float2 rv0 = *(const float2*)(R + (size_t)r0 * N + c);
                float2 rv1 = *(const float2*)(R + (size_t)r1 * N + c);
                v0.x += rv0.x; v0.y += rv0.y;
                v1.x += rv1.x; v1.y += rv1.y;
            }
            if (EPI == 2) {
                v0.x = gelu_erf(v0.x); v0.y = gelu_erf(v0.y);
                v1.x = gelu_erf(v1.x); v1.y = gelu_erf(v1.y);
            }
            *(float2*)(C + (size_t)r0 * N + c) = v0;
            *(float2*)(C + (size_t)r1 * N + c) = v1;
        }
    }
}

// ---------------- tf32 tensor-core flash attention (causal, dk=64) ----------------
// 128 threads = 4 warps; warp w owns q-rows [w*16, w*16+16) of a 64-row tile.
// Smem: Qs[64][68] (pre-scaled tf32), Ks[64][68], Vt[64][68] (V transposed).
#define FQP 68
#define FSM (3*64*FQP*4)

__global__ void __launch_bounds__(128)
flash_tc(const float* __restrict__ q, const float* __restrict__ k,
         const float* __restrict__ v, float* __restrict__ o) {
    extern __shared__ float sm[];
    float (*Qs)[FQP] = (float(*)[FQP])(sm);
    float (*Ks)[FQP] = (float(*)[FQP])(sm + 64*FQP);
    float (*Vt)[FQP] = (float(*)[FQP])(sm + 2*64*FQP);

    int qi = blockIdx.x;
    int bh = blockIdx.y;
    int b = bh >> 4, h = bh & 15;
    const float* qp    = q + ((size_t)(b*SS + qi*64)) * DD + h*DKH;
    const float* kbase = k + (size_t)b * SS * DD + h*DKH;
    const float* vbase = v + (size_t)b * SS * DD + h*DKH;

    int tid = threadIdx.x;
    int w = tid >> 5, lane = tid & 31;
    int tg = lane >> 2, tq = lane & 3;

    // Load Q (fold 1/sqrt(dk)=0.125 into Q), coalesced: 1024 float4 over 128 threads
    #pragma unroll
    for (int i = 0; i < 8; i++) {
        int f = tid + i * 128;
        int r = f >> 4, c = (f & 15) * 4;
        float4 t4 = *(const float4*)(qp + (size_t)r * DD + c);
        Qs[r][c+0] = to_tf32(t4.x * 0.125f);
        Qs[r][c+1] = to_tf32(t4.y * 0.125f);
        Qs[r][c+2] = to_tf32(t4.z * 0.125f);
        Qs[r][c+3] = to_tf32(t4.w * 0.125f);
    }

    float ofrag[8][4];
    #pragma unroll
    for (int nt = 0; nt < 8; nt++)
        #pragma unroll
        for (int j = 0; j < 4; j++) ofrag[nt][j] = 0.f;
    float mrow0 = -INFINITY, mrow1 = -INFINITY, lrow0 = 0.f, lrow1 = 0.f;

    for (int jt = 0; jt <= qi; jt++) {
        __syncthreads();   // prior PV reads done before overwrite
        // Load K (straight) and V (transposed)
        #pragma unroll
        for (int i = 0; i < 8; i++) {
            int f = tid + i * 128;
            int r = f >> 4, c = (f & 15) * 4;
            const float* kp = kbase + (size_t)(jt*64 + r) * DD + c;
            float4 t4 = *(const float4*)(kp);
            Ks[r][c+0] = to_tf32(t4.x); Ks[r][c+1] = to_tf32(t4.y);
            Ks[r][c+2] = to_tf32(t4.z); Ks[r][c+3] = to_tf32(t4.w);
            const float* vp = vbase + (size_t)(jt*64 + r) * DD + c;
            float4 u4 = *(const float4*)(vp);
            Vt[c+0][r] = to_tf32(u4.x); Vt[c+1][r] = to_tf32(u4.y);
            Vt[c+2][r] = to_tf32(u4.z); Vt[c+3][r] = to_tf32(u4.w);
        }
        __syncthreads();

        // S = Q K^T : warp computes 16x64 via 8 n-tiles, 8 k-steps
        float s[8][4];
        #pragma unroll
        for (int nt = 0; nt < 8; nt++)
            #pragma unroll
            for (int j = 0; j < 4; j++) s[nt][j] = 0.f;
        #pragma unroll
        for (int kb8 = 0; kb8 < 8; kb8++) {
            int kb = kb8 * 8;
            int r = w * 16;
            uint32_t a0 = __float_as_uint(Qs[r + tg][kb + tq]);
            uint32_t a1 = __float_as_uint(Qs[r + tg + 8][kb + tq]);
            uint32_t a2 = __float_as_uint(Qs[r + tg][kb + tq + 4]);
            uint32_t a3 = __float_as_uint(Qs[r + tg + 8][kb + tq + 4]);
            #pragma unroll
            for (int nt = 0; nt < 8; nt++) {
                uint32_t b0 = __float_as_uint(Ks[nt*8 + tg][kb + tq]);
                uint32_t b1 = __float_as_uint(Ks[nt*8 + tg][kb + tq + 4]);
                mma_tf32(s[nt], a0, a1, a2, a3, b0, b1);
            }
        }

        // causal mask on diagonal tile (tile-local rows/cols)
        if (jt == qi) {
            int r0 = w*16 + tg, r1 = r0 + 8;
            #pragma unroll
            for (int nt = 0; nt < 8; nt++) {
                int c0 = nt*8 + 2*tq, c1 = c0 + 1;
                if (c0 > r0) s[nt][0] = -INFINITY;
                if (c1 > r0) s[nt][1] = -INFINITY;
                if (c0 > r1) s[nt][2] = -INFINITY;
                if (c1 > r1) s[nt][3] = -INFINITY;
            }
        }

        // row maxes (quad reduce: lanes sharing tg differ only in tq)
        float m0 = -INFINITY, m1 = -INFINITY;
        #pragma unroll
        for (int nt = 0; nt < 8; nt++) {
            m0 = fmaxf(m0, fmaxf(s[nt][0], s[nt][1]));
            m1 = fmaxf(m1, fmaxf(s[nt][2], s[nt][3]));
        }
        m0 = fmaxf(m0, __shfl_xor_sync(0xffffffffu, m0, 1));
        m0 = fmaxf(m0, __shfl_xor_sync(0xffffffffu, m0, 2));
        m1 = fmaxf(m1, __shfl_xor_sync(0xffffffffu, m1, 1));
        m1 = fmaxf(m1, __shfl_xor_sync(0xffffffffu, m1, 2));

        float mn0 = fmaxf(mrow0, m0), mn1 = fmaxf(mrow1, m1);
        float corr0 = __expf(mrow0 - mn0), corr1 = __expf(mrow1 - mn1);
        mrow0 = mn0; mrow1 = mn1;

        float rs0 = 0.f, rs1 = 0.f;
        uint32_t pu[8][4];
        #pragma unroll
        for (int nt = 0; nt < 8; nt++) {
            float p0 = __expf(s[nt][0] - mn0);
            float p1 = __expf(s[nt][1] - mn0);
            float p2 = __expf(s[nt][2] - mn1);
            float p3 = __expf(s[nt][3] - mn1);
            rs0 += p0 + p1; rs1 += p2 + p3;
            pu[nt][0] = __float_as_uint(to_tf32(p0));
            pu[nt][1] = __float_as_uint(to_tf32(p1));
            pu[nt][2] = __float_as_uint(to_tf32(p2));
            pu[nt][3] = __float_as_uint(to_tf32(p3));
            ofrag[nt][0] *= corr0; ofrag[nt][1] *= corr0;
            ofrag[nt][2] *= corr1; ofrag[nt][3] *= corr1;
        }
        rs0 += __shfl_xor_sync(0xffffffffu, rs0, 1);
        rs0 += __shfl_xor_sync(0xffffffffu, rs0, 2);
        rs1 += __shfl_xor_sync(0xffffffffu, rs1, 1);
        rs1 += __shfl_xor_sync(0xffffffffu, rs1, 2);
        lrow0 = lrow0 * corr0 + rs0;
        lrow1 = lrow1 * corr1 + rs1;

        // O += P V : reshape P frag (C layout) -> A layout via quad shuffles
        int srcl = (lane & 0x1c) | (tq >> 1);
        #pragma unroll
        for (int kt = 0; kt < 8; kt++) {
            uint32_t u00 = __shfl_sync(0xffffffffu, pu[kt][0], srcl);
            uint32_t u01 = __shfl_sync(0xffffffffu, pu[kt][1], srcl);
            uint32_t u10 = __shfl_sync(0xffffffffu, pu[kt][2], srcl);
            uint32_t u11 = __shfl_sync(0xffffffffu, pu[kt][3], srcl);
            uint32_t u20 = __shfl_sync(0xffffffffu, pu[kt][0], srcl + 2);
            uint32_t u21 = __shfl_sync(0xffffffffu, pu[kt][1], srcl + 2);
            uint32_t u30 = __shfl_sync(0xffffffffu, pu[kt][2], srcl + 2);
            uint32_t u31 = __shfl_sync(0xffffffffu, pu[kt][3], srcl + 2);
            bool odd = (tq & 1);
            uint32_t a0 = odd ? u01 : u00;
            uint32_t a1 = odd ? u11 : u10;
            uint32_t a2 = odd ? u21 : u20;
            uint32_t a3 = odd ? u31 : u30;
            int kb = kt * 8;
            #pragma unroll
            for (int nt = 0; nt < 8; nt++) {
                uint32_t b0 = __float_as_uint(Vt[nt*8 + tg][kb + tq]);
                uint32_t b1 = __float_as_uint(Vt[nt*8 + tg][kb + tq + 4]);
                mma_tf32(ofrag[nt], a0, a1, a2, a3, b0, b1);
            }
        }
    }

    // write O
    float inv0 = 1.0f / lrow0, inv1 = 1.0f / lrow1;
    int r0 = qi*64 + w*16 + tg, r1 = r0 + 8;
    float* op = o + (size_t)(b*SS) * DD + h*DKH;
    #pragma unroll
    for (int nt = 0; nt < 8; nt++) {
        int c = nt*8 + 2*tq;
        *(float2*)(op + (size_t)r0 * DD + c) =
            make_float2(ofrag[nt][0]*inv0, ofrag[nt][1]*inv0);
        *(float2*)(op + (size_t)r1 * DD + c) =
            make_float2(ofrag[nt][2]*inv1, ofrag[nt][3]*inv1);
    }
}

// ---------------- launch ----------------
extern "C" void kernel_launch(void* const* d_in, const int* in_sizes, int n_in,
                              void* d_out, int out_size) {
    const float* x  = (const float*)d_in[0];
    const float* g1 = (const float*)d_in[1];
    const float* g2 = (const float*)d_in[2];
    const float* wq = (const float*)d_in[3];
    const float* wk = (const float*)d_in[4];
    const float* wv = (const float*)d_in[5];
    const float* wo = (const float*)d_in[6];
    const float* w1 = (const float*)d_in[7];
    const float* w2 = (const float*)d_in[8];
    float* out = (float*)d_out;

    float *xn, *q, *k, *v, *att, *x1, *xn2, *ff;
    cudaGetSymbolAddress((void**)&xn,  g_xn);
    cudaGetSymbolAddress((void**)&q,   g_q);
    cudaGetSymbolAddress((void**)&k,   g_k);
    cudaGetSymbolAddress((void**)&v,   g_v);
    cudaGetSymbolAddress((void**)&att, g_att);
    cudaGetSymbolAddress((void**)&x1,  g_x1);
    cudaGetSymbolAddress((void**)&xn2, g_xn2);
    cudaGetSymbolAddress((void**)&ff,  g_ff);

    cudaFuncSetAttribute(flash_tc,
                         cudaFuncAttributeMaxDynamicSharedMemorySize, FSM);

    dim3 gD(DD/128, MM/128);    // N=1024 GEMMs
    dim3 gF(DFF/128, MM/128);   // N=4096 GEMM

    // 1. xn = rmsnorm(x, g1)
    rmsnorm_kernel<<<MM, 256>>>(x, g1, xn);
    // 2. Q, K, V projections (tf32 tensor cores)
    gemm_tc<0><<<gD, 256>>>(xn, wq, nullptr, q, MM, DD, DD);
    gemm_tc<0><<<gD, 256>>>(xn, wk, nullptr, k, MM, DD, DD);
    gemm_tc<0><<<gD, 256>>>(xn, wv, nullptr, v, MM, DD, DD);
    // 3. causal flash attention (tf32 tensor cores)
    flash_tc<<<dim3(SS/64, BB*HH), 128, FSM>>>(q, k, v, att);
    // 4. x1 = x + att @ wo^T
    gemm_tc<1><<<gD, 256>>>(att, wo, x, x1, MM, DD, DD);
    // 5. xn2 = rmsnorm(x1, g2)
    rmsnorm_kernel<<<MM, 256>>>(x1, g2, xn2);
    // 6. ff = gelu(xn2 @ w1^T)
    gemm_tc<2><<<gF, 256>>>(xn2, w1, nullptr, ff, MM, DFF, DD);
    // 7. out = x1 + ff @ w2^T
    gemm_tc<1><<<gD, 256>>>(ff, w2, x1, out, MM, DD, DFF);
}

// round 6
// speedup vs baseline: 3.0665x; 1.0724x over previous
#include <cuda_runtime.h>
#include <math.h>
#include <stdint.h>

#define BB   2
#define SS   2048
#define DD   1024
#define HH   16
#define DKH  64
#define DFF  4096
#define MM   (BB*SS)     // 4096 rows total
#define EPSV 1e-5f

// ---------------- scratch (device globals: allocation-free) ----------------
__device__ float g_xn  [MM*DD];
__device__ float g_qkv [MM*3*DD];   // fused QKV output [M, 3072]
__device__ float g_att [MM*DD];
__device__ float g_x1  [MM*DD];
__device__ float g_xn2 [MM*DD];
__device__ float g_ff  [MM*DFF];
__device__ float g_wqkv[3*DD*DD];   // tf32-rounded [wq;wk;wv]
__device__ float g_woc [DD*DD];
__device__ float g_w1c [DFF*DD];
__device__ float g_w2c [DD*DFF];

// ---------------- small helpers ----------------
__device__ __forceinline__ float to_tf32(float x) {
    float r;
    asm("cvt.rna.tf32.f32 %0, %1;" : "=f"(r) : "f"(x));
    return r;
}
__device__ __forceinline__ float gelu_erf(float x) {
    return 0.5f * x * (1.0f + erff(x * 0.70710678118654752f));
}
__device__ __forceinline__ uint32_t smem_u32(const void* p) {
    uint32_t a;
    asm("{ .reg .u64 t; cvta.to.shared.u64 t, %1; cvt.u32.u64 %0, t; }"
        : "=r"(a) : "l"(p));
    return a;
}
__device__ __forceinline__ void cp16(uint32_t smaddr, const void* gptr) {
    asm volatile("cp.async.cg.shared.global [%0], [%1], 16;"
                 :: "r"(smaddr), "l"(gptr) : "memory");
}
#define CP_COMMIT() asm volatile("cp.async.commit_group;" ::: "memory")

__device__ __forceinline__ void mma_tf32(float c[4],
                                         uint32_t a0, uint32_t a1, uint32_t a2, uint32_t a3,
                                         uint32_t b0, uint32_t b1) {
    asm volatile(
        "mma.sync.aligned.m16n8k8.row.col.f32.tf32.tf32.f32 "
        "{%0,%1,%2,%3},{%4,%5,%6,%7},{%8,%9},{%0,%1,%2,%3};"
        : "+f"(c[0]), "+f"(c[1]), "+f"(c[2]), "+f"(c[3])
        : "r"(a0), "r"(a1), "r"(a2), "r"(a3), "r"(b0), "r"(b1));
}

// ---------------- RMSNorm (output rounded to tf32) ----------------
__global__ void rmsnorm_kernel(const float* __restrict__ x,
                               const float* __restrict__ g,
                               float* __restrict__ out) {
    int row = blockIdx.x;
    int t = threadIdx.x;
    float4 v = ((const float4*)(x + (size_t)row * DD))[t];
    float s = v.x*v.x + v.y*v.y + v.z*v.z + v.w*v.w;
    #pragma unroll
    for (int o = 16; o; o >>= 1) s += __shfl_xor_sync(0xffffffffu, s, o);
    __shared__ float ws[8];
    __shared__ float tot;
    if ((t & 31) == 0) ws[t >> 5] = s;
    __syncthreads();
    if (t == 0) {
        float z = 0.f;
        #pragma unroll
        for (int i = 0; i < 8; i++) z += ws[i];
        tot = rsqrtf(z * (1.0f / DD) + EPSV);
    }
    __syncthreads();
    float rn = tot;
    float4 gv = ((const float4*)g)[t];
    float4 ov = make_float4(to_tf32(v.x*rn*gv.x), to_tf32(v.y*rn*gv.y),
                            to_tf32(v.z*rn*gv.z), to_tf32(v.w*rn*gv.w));
    ((float4*)(out + (size_t)row * DD))[t] = ov;
}

// ---------------- weight convert (round to tf32) ----------------
__global__ void cvt_copy(const float* __restrict__ src, float* __restrict__ dst, int n4) {
    int i = blockIdx.x * blockDim.x + threadIdx.x;
    int stride = gridDim.x * blockDim.x;
    for (; i < n4; i += stride) {
        float4 v = ((const float4*)src)[i];
        ((float4*)dst)[i] = make_float4(to_tf32(v.x), to_tf32(v.y),
                                        to_tf32(v.z), to_tf32(v.w));
    }
}

// ---------------- cp.async tf32 mma GEMM: C[M,N] = A[M,K] * B[N,K]^T ----------------
// 128x128 CTA tile, 256 threads (8 warps: 2 along M x 4 along N), warp tile 64x32.
// 4-stage cp.async pipeline, k-slab 16, smem pitch 20 (conflict-free frags, 16B aligned).
#define GS      4
#define KSLAB   16
#define APITCH  20
#define STAGEW  (128*APITCH)         // floats per matrix per stage (2560)
#define STAGE_B (STAGEW*4)           // 10240 bytes
#define PAIR_B  (2*STAGE_B)          // 20480 bytes
#define GSMEM   (GS*PAIR_B)          // 81920 bytes

// EPI: 0 = none, 1 = +R (residual), 2 = gelu_erf (tf32-rounded)
template<int EPI>
__global__ void __launch_bounds__(256, 2)
gemm_cp(const float* __restrict__ A, const float* __restrict__ B,
        const float* __restrict__ R, float* __restrict__ C,
        int M, int N, int K) {
    extern __shared__ __align__(16) float smp[];
    uint32_t sb = smem_u32(smp);
    int tid = threadIdx.x;
    int wid = tid >> 5, lane = tid & 31;
    int warp_m = (wid & 1) * 64;
    int warp_n = (wid >> 1) * 32;
    int tg = lane >> 2, tq = lane & 3;
    int bm = blockIdx.y * 128, bn = blockIdx.x * 128;

    // loader map: thread -> (row tid>>2 in [0,64), 16B chunk tid&3); second row +64
    int r0 = tid >> 2;
    int c16 = tid & 3;
    const float* Ap = A + (size_t)(bm + r0) * K + c16 * 4;
    const float* Bp = B + (size_t)(bn + r0) * K + c16 * 4;
    uint32_t soff = (uint32_t)(r0 * APITCH * 4 + c16 * 16);
    const uint32_t rowB = 64u * APITCH * 4u;   // +64 rows in bytes

    float acc[4][4][4];
    #pragma unroll
    for (int i = 0; i < 4; i++)
        #pragma unroll
        for (int j = 0; j < 4; j++)
            #pragma unroll
            for (int q = 0; q < 4; q++) acc[i][j][q] = 0.f;

    int NS = K / KSLAB;

    // prologue: stages 0..GS-2
    #pragma unroll
    for (int p = 0; p < GS - 1; p++) {
        uint32_t da = sb + p * PAIR_B + soff;
        uint32_t db = da + STAGE_B;
        cp16(da,        Ap + p * KSLAB);
        cp16(da + rowB, Ap + (size_t)64 * K + p * KSLAB);
        cp16(db,        Bp + p * KSLAB);
        cp16(db + rowB, Bp + (size_t)64 * K + p * KSLAB);
        CP_COMMIT();
    }

    for (int slab = 0; slab < NS; slab++) {
        asm volatile("cp.async.wait_group %0;" :: "n"(GS - 2) : "memory");
        __syncthreads();   // slab's stage visible; previous compute done

        // issue loads for slab+GS-1 (buffer freed by compute of slab-1)
        int t = slab + GS - 1;
        if (t < NS) {
            uint32_t da = sb + (t % GS) * PAIR_B + soff;
            uint32_t db = da + STAGE_B;
            cp16(da,        Ap + t * KSLAB);
            cp16(da + rowB, Ap + (size_t)64 * K + t * KSLAB);
            cp16(db,        Bp + t * KSLAB);
            cp16(db + rowB, Bp + (size_t)64 * K + t * KSLAB);
        }
        CP_COMMIT();       // empty group at tail keeps wait_group bookkeeping exact

        const float* As = smp + (slab % GS) * (2 * STAGEW);
        const float* Bs = As + STAGEW;
        #pragma unroll
        for (int kt = 0; kt < 2; kt++) {
            int kb = kt * 8;
            uint32_t af[4][4];
            #pragma unroll
            for (int mt = 0; mt < 4; mt++) {
                int r = warp_m + mt * 16;
                af[mt][0] = __float_as_uint(As[(r + tg) * APITCH + kb + tq]);
                af[mt][1] = __float_as_uint(As[(r + tg + 8) * APITCH + kb + tq]);
                af[mt][2] = __float_as_uint(As[(r + tg) * APITCH + kb + tq + 4]);
                af[mt][3] = __float_as_uint(As[(r + tg + 8) * APITCH + kb + tq + 4]);
            }
            uint32_t bf[4][2];
            #pragma unroll
            for (int nt = 0; nt < 4; nt++) {
                int c = warp_n + nt * 8;
                bf[nt][0] = __float_as_uint(Bs[(c + tg) * APITCH + kb + tq]);
                bf[nt][1] = __float_as_uint(Bs[(c + tg) * APITCH + kb + tq + 4]);
            }
            #pragma unroll
            for (int mt = 0; mt < 4; mt++)
                #pragma unroll
                for (int nt = 0; nt < 4; nt++)
                    mma_tf32(acc[mt][nt], af[mt][0], af[mt][1], af[mt][2], af[mt][3],
                             bf[nt][0], bf[nt][1]);
        }
    }

    // epilogue
    #pragma unroll
    for (int mt = 0; mt < 4; mt++) {
        #pragma unroll
        for (int nt = 0; nt < 4; nt++) {
            int r0o = bm + warp_m + mt * 16 + tg;
            int r1o = r0o + 8;
            int c = bn + warp_n + nt * 8 + tq * 2;
            float2 v0 = make_float2(acc[mt][nt][0], acc[mt][nt][1]);
            float2 v1 = make_float2(acc[mt][nt][2], acc[mt][nt][3]);
            if (EPI == 1) {
                float2 rv0 = *(const float2*)(R + (size_t)r0o * N + c);
                float2 rv1 = *(const float2*)(R + (size_t)r1o * N + c);
                v0.x += rv0.x; v0.y += rv0.y;
                v1.x += rv1.x; v1.y += rv1.y;
            }
            if (EPI == 2) {
                v0.x = to_tf32(gelu_erf(v0.x)); v0.y = to_tf32(gelu_erf(v0.y));
                v1.x = to_tf32(gelu_erf(v1.x)); v1.y = to_tf32(gelu_erf(v1.y));
            }
            *(float2*)(C + (size_t)r0o * N + c) = v0;
            *(float2*)(C + (size_t)r1o * N + c) = v1;
        }
    }
}

// ---------------- tf32 tensor-core flash attention (causal, dk=64) ----------------
// q/k/v strided (fused QKV layout); output att rounded to tf32.
#define FQP 68
#define FSM (3*64*FQP*4)

__global__ void __launch_bounds__(128)
flash_tc(const float* __restrict__ q, const float* __restrict__ k,
         const float* __restrict__ v, float* __restrict__ o, int ldq) {
    extern __shared__ float smf[];
    float (*Qs)[FQP] = (float(*)[FQP])(smf);
    float (*Ks)[FQP] = (float(*)[FQP])(smf + 64*FQP);
    float (*Vt)[FQP] = (float(*)[FQP])(smf + 2*64*FQP);

    int qi = blockIdx.x;
    int bh = blockIdx.y;
    int b = bh >> 4, h = bh & 15;
    const float* qp    = q + ((size_t)(b*SS + qi*64)) * ldq + h*DKH;
    const float* kbase = k + (size_t)b * SS * ldq + h*DKH;
    const float* vbase = v + (size_t)b * SS * ldq + h*DKH;

    int tid = threadIdx.x;
    int w = tid >> 5, lane = tid & 31;
    int tg = lane >> 2, tq = lane & 3;

    #pragma unroll
    for (int i = 0; i < 8; i++) {
        int f = tid + i * 128;
        int r = f >> 4, c = (f & 15) * 4;
        float4 t4 = *(const float4*)(qp + (size_t)r * ldq + c);
        Qs[r][c+0] = to_tf32(t4.x * 0.125f);
        Qs[r][c+1] = to_tf32(t4.y * 0.125f);
        Qs[r][c+2] = to_tf32(t4.z * 0.125f);
        Qs[r][c+3] = to_tf32(t4.w * 0.125f);
    }

    float ofrag[8][4];
    #pragma unroll
    for (int nt = 0; nt < 8; nt++)
        #pragma unroll
        for (int j = 0; j < 4; j++) ofrag[nt][j] = 0.f;
    float mrow0 = -INFINITY, mrow1 = -INFINITY, lrow0 = 0.f, lrow1 = 0.f;

    for (int jt = 0; jt <= qi; jt++) {
        __syncthreads();
        #pragma unroll
        for (int i = 0; i < 8; i++) {
            int f = tid + i * 128;
            int r = f >> 4, c = (f & 15) * 4;
            const float* kp = kbase + (size_t)(jt*64 + r) * ldq + c;
            float4 t4 = *(const float4*)(kp);
            Ks[r][c+0] = to_tf32(t4.x); Ks[r][c+1] = to_tf32(t4.y);
            Ks[r][c+2] = to_tf32(t4.z); Ks[r][c+3] = to_tf32(t4.w);
            const float* vp = vbase + (size_t)(jt*64 + r) * ldq + c;
            float4 u4 = *(const float4*)(vp);
            Vt[c+0][r] = to_tf32(u4.x); Vt[c+1][r] = to_tf32(u4.y);
            Vt[c+2][r] = to_tf32(u4.z); Vt[c+3][r] = to_tf32(u4.w);
        }
        __syncthreads();

        float s[8][4];
        #pragma unroll
        for (int nt = 0; nt < 8; nt++)
            #pragma unroll
            for (int j = 0; j < 4; j++) s[nt][j] = 0.f;
        #pragma unroll
        for (int kb8 = 0; kb8 < 8; kb8++) {
            int kb = kb8 * 8;
            int r = w * 16;
            uint32_t a0 = __float_as_uint(Qs[r + tg][kb + tq]);
            uint32_t a1 = __float_as_uint(Qs[r + tg + 8][kb + tq]);
            uint32_t a2 = __float_as_uint(Qs[r + tg][kb + tq + 4]);
            uint32_t a3 = __float_as_uint(Qs[r + tg + 8][kb + tq + 4]);
            #pragma unroll
            for (int nt = 0; nt < 8; nt++) {
                uint32_t b0 = __float_as_uint(Ks[nt*8 + tg][kb + tq]);
                uint32_t b1 = __float_as_uint(Ks[nt*8 + tg][kb + tq + 4]);
                mma_tf32(s[nt], a0, a1, a2, a3, b0, b1);
            }
        }

        if (jt == qi) {
            int r0 = w*16 + tg, r1 = r0 + 8;
            #pragma unroll
            for (int nt = 0; nt < 8; nt++) {
                int c0 = nt*8 + 2*tq, c1 = c0 + 1;
                if (c0 > r0) s[nt][0] = -INFINITY;
                if (c1 > r0) s[nt][1] = -INFINITY;
                if (c0 > r1) s[nt][2] = -INFINITY;
                if (c1 > r1) s[nt][3] = -INFINITY;
            }
        }

        float m0 = -INFINITY, m1 = -INFINITY;
        #pragma unroll
        for (int nt = 0; nt < 8; nt++) {
            m0 = fmaxf(m0, fmaxf(s[nt][0], s[nt][1]));
            m1 = fmaxf(m1, fmaxf(s[nt][2], s[nt][3]));
        }
        m0 = fmaxf(m0, __shfl_xor_sync(0xffffffffu, m0, 1));
        m0 = fmaxf(m0, __shfl_xor_sync(0xffffffffu, m0, 2));
        m1 = fmaxf(m1, __shfl_xor_sync(0xffffffffu, m1, 1));
        m1 = fmaxf(m1, __shfl_xor_sync(0xffffffffu, m1, 2));

        float mn0 = fmaxf(mrow0, m0), mn1 = fmaxf(mrow1, m1);
        float corr0 = __expf(mrow0 - mn0), corr1 = __expf(mrow1 - mn1);
        mrow0 = mn0; mrow1 = mn1;

        float rs0 = 0.f, rs1 = 0.f;
        uint32_t pu[8][4];
        #pragma unroll
        for (int nt = 0; nt < 8; nt++) {
            float p0 = __expf(s[nt][0] - mn0);
            float p1 = __expf(s[nt][1] - mn0);
            float p2 = __expf(s[nt][2] - mn1);
            float p3 = __expf(s[nt][3] - mn1);
            rs0 += p0 + p1; rs1 += p2 + p3;
            pu[nt][0] = __float_as_uint(to_tf32(p0));
            pu[nt][1] = __float_as_uint(to_tf32(p1));
            pu[nt][2] = __float_as_uint(to_tf32(p2));
            pu[nt][3] = __float_as_uint(to_tf32(p3));
            ofrag[nt][0] *= corr0; ofrag[nt][1] *= corr0;
            ofrag[nt][2] *= corr1; ofrag[nt][3] *= corr1;
        }
        rs0 += __shfl_xor_sync(0xffffffffu, rs0, 1);
        rs0 += __shfl_xor_sync(0xffffffffu, rs0, 2);
        rs1 += __shfl_xor_sync(0xffffffffu, rs1, 1);
        rs1 += __shfl_xor_sync(0xffffffffu, rs1, 2);
        lrow0 = lrow0 * corr0 + rs0;
        lrow1 = lrow1 * corr1 + rs1;

        int srcl = (lane & 0x1c) | (tq >> 1);
        #pragma unroll
        for (int kt = 0; kt < 8; kt++) {
            uint32_t u00 = __shfl_sync(0xffffffffu, pu[kt][0], srcl);
            uint32_t u01 = __shfl_sync(0xffffffffu, pu[kt][1], srcl);
            uint32_t u10 = __shfl_sync(0xffffffffu, pu[kt][2], srcl);
            uint32_t u11 = __shfl_sync(0xffffffffu, pu[kt][3], srcl);
            uint32_t u20 = __shfl_sync(0xffffffffu, pu[kt][0], srcl + 2);
            uint32_t u21 = __shfl_sync(0xffffffffu, pu[kt][1], srcl + 2);
            uint32_t u30 = __shfl_sync(0xffffffffu, pu[kt][2], srcl + 2);
            uint32_t u31 = __shfl_sync(0xffffffffu, pu[kt][3], srcl + 2);
            bool odd = (tq & 1);
            uint32_t a0 = odd ? u01 : u00;
            uint32_t a1 = odd ? u11 : u10;
            uint32_t a2 = odd ? u21 : u20;
            uint32_t a3 = odd ? u31 : u30;
            int kb = kt * 8;
            #pragma unroll
            for (int nt = 0; nt < 8; nt++) {
                uint32_t b0 = __float_as_uint(Vt[nt*8 + tg][kb + tq]);
                uint32_t b1 = __float_as_uint(Vt[nt*8 + tg][kb + tq + 4]);
                mma_tf32(ofrag[nt], a0, a1, a2, a3, b0, b1);
            }
        }
    }

    float inv0 = 1.0f / lrow0, inv1 = 1.0f / lrow1;
    int r0 = qi*64 + w*16 + tg, r1 = r0 + 8;
    float* op = o + (size_t)(b*SS) * DD + h*DKH;
    #pragma unroll
    for (int nt = 0; nt < 8; nt++) {
        int c = nt*8 + 2*tq;
        *(float2*)(op + (size_t)r0 * DD + c) =
            make_float2(to_tf32(ofrag[nt][0]*inv0), to_tf32(ofrag[nt][1]*inv0));
        *(float2*)(op + (size_t)r1 * DD + c) =
            make_float2(to_tf32(ofrag[nt][2]*inv1), to_tf32(ofrag[nt][3]*inv1));
    }
}

// ---------------- launch ----------------
extern "C" void kernel_launch(void* const* d_in, const int* in_sizes, int n_in,
                              void* d_out, int out_size) {
    const float* x  = (const float*)d_in[0];
    const float* g1 = (const float*)d_in[1];
    const float* g2 = (const float*)d_in[2];
    const float* wq = (const float*)d_in[3];
    const float* wk = (const float*)d_in[4];
    const float* wv = (const float*)d_in[5];
    const float* wo = (const float*)d_in[6];
    const float* w1 = (const float*)d_in[7];
    const float* w2 = (const float*)d_in[8];
    float* out = (float*)d_out;

    float *xn, *qkv, *att, *x1, *xn2, *ff, *wqkvc, *woc, *w1c, *w2c;
    cudaGetSymbolAddress((void**)&xn,    g_xn);
    cudaGetSymbolAddress((void**)&qkv,   g_qkv);
    cudaGetSymbolAddress((void**)&att,   g_att);
    cudaGetSymbolAddress((void**)&x1,    g_x1);
    cudaGetSymbolAddress((void**)&xn2,   g_xn2);
    cudaGetSymbolAddress((void**)&ff,    g_ff);
    cudaGetSymbolAddress((void**)&wqkvc, g_wqkv);
    cudaGetSymbolAddress((void**)&woc,   g_woc);
    cudaGetSymbolAddress((void**)&w1c,   g_w1c);
    cudaGetSymbolAddress((void**)&w2c,   g_w2c);

    cudaFuncSetAttribute(flash_tc,
                         cudaFuncAttributeMaxDynamicSharedMemorySize, FSM);
    cudaFuncSetAttribute(gemm_cp<0>,
                         cudaFuncAttributeMaxDynamicSharedMemorySize, GSMEM);
    cudaFuncSetAttribute(gemm_cp<1>,
                         cudaFuncAttributeMaxDynamicSharedMemorySize, GSMEM);
    cudaFuncSetAttribute(gemm_cp<2>,
                         cudaFuncAttributeMaxDynamicSharedMemorySize, GSMEM);

    // weight conversion (tf32 rounding) — cheap, graph-capturable
    cvt_copy<<<256, 256>>>(wq, wqkvc,            DD*DD/4);
    cvt_copy<<<256, 256>>>(wk, wqkvc + DD*DD,    DD*DD/4);
    cvt_copy<<<256, 256>>>(wv, wqkvc + 2*DD*DD,  DD*DD/4);
    cvt_copy<<<256, 256>>>(wo, woc,              DD*DD/4);
    cvt_copy<<<512, 256>>>(w1, w1c,              DFF*DD/4);
    cvt_copy<<<512, 256>>>(w2, w2c,              DD*DFF/4);

    // 1. xn = rmsnorm(x, g1)  (tf32-rounded)
    rmsnorm_kernel<<<MM, 256>>>(x, g1, xn);
    // 2. fused QKV: qkv[M,3072] = xn @ [wq;wk;wv]^T
    gemm_cp<0><<<dim3(3*DD/128, MM/128), 256, GSMEM>>>(xn, wqkvc, nullptr, qkv,
                                                       MM, 3*DD, DD);
    // 3. causal flash attention (q,k,v strided within qkv)
    flash_tc<<<dim3(SS/64, BB*HH), 128, FSM>>>(qkv, qkv + DD, qkv + 2*DD, att, 3*DD);
    // 4. x1 = x + att @ wo^T
    gemm_cp<1><<<dim3(DD/128, MM/128), 256, GSMEM>>>(att, woc, x, x1, MM, DD, DD);
    // 5. xn2 = rmsnorm(x1, g2)  (tf32-rounded)
    rmsnorm_kernel<<<MM, 256>>>(x1, g2, xn2);
    // 6. ff = gelu(xn2 @ w1^T)  (tf32-rounded)
    gemm_cp<2><<<dim3(DFF/128, MM/128), 256, GSMEM>>>(xn2, w1c, nullptr, ff,
                                                      MM, DFF, DD);
    // 7. out = x1 + ff @ w2^T
    gemm_cp<1><<<dim3(DD/128, MM/128), 256, GSMEM>>>(ff, w2c, x1, out, MM, DD, DFF);
}

// round 7
// speedup vs baseline: 5.3225x; 1.7357x over previous
#include <cuda_runtime.h>
#include <cuda_fp16.h>
#include <math.h>
#include <stdint.h>

#define BB   2
#define SS   2048
#define DD   1024
#define HH   16
#define DKH  64
#define DFF  4096
#define MM   (BB*SS)     // 4096 rows total
#define EPSV 1e-5f

// ---------------- scratch (device globals: allocation-free) ----------------
__device__ __half g_xn  [MM*DD];
__device__ __half g_qkv [MM*3*DD];   // fused QKV output [M, 3072]
__device__ __half g_att [MM*DD];
__device__ float  g_x1  [MM*DD];     // residual carrier stays fp32
__device__ __half g_xn2 [MM*DD];
__device__ __half g_ff  [MM*DFF];
__device__ __half g_wqkv[3*DD*DD];
__device__ __half g_woc [DD*DD];
__device__ __half g_w1c [DFF*DD];
__device__ __half g_w2c [DD*DFF];

// ---------------- small helpers ----------------
__device__ __forceinline__ float to_tf32(float x) {
    float r;
    asm("cvt.rna.tf32.f32 %0, %1;" : "=f"(r) : "f"(x));
    return r;
}
__device__ __forceinline__ float gelu_erf(float x) {
    return 0.5f * x * (1.0f + erff(x * 0.70710678118654752f));
}
__device__ __forceinline__ uint32_t smem_u32(const void* p) {
    uint32_t a;
    asm("{ .reg .u64 t; cvta.to.shared.u64 t, %1; cvt.u32.u64 %0, t; }"
        : "=r"(a) : "l"(p));
    return a;
}
__device__ __forceinline__ void cp16(uint32_t smaddr, const void* gptr) {
    asm volatile("cp.async.cg.shared.global [%0], [%1], 16;"
                 :: "r"(smaddr), "l"(gptr) : "memory");
}
#define CP_COMMIT() asm volatile("cp.async.commit_group;" ::: "memory")

__device__ __forceinline__ void ldsm4(uint32_t& r0, uint32_t& r1,
                                      uint32_t& r2, uint32_t& r3, uint32_t a) {
    asm volatile("ldmatrix.sync.aligned.m8n8.x4.shared.b16 {%0,%1,%2,%3}, [%4];"
                 : "=r"(r0), "=r"(r1), "=r"(r2), "=r"(r3) : "r"(a));
}
__device__ __forceinline__ void mma_f16(float c[4],
                                        uint32_t a0, uint32_t a1, uint32_t a2, uint32_t a3,
                                        uint32_t b0, uint32_t b1) {
    asm volatile(
        "mma.sync.aligned.m16n8k16.row.col.f32.f16.f16.f32 "
        "{%0,%1,%2,%3},{%4,%5,%6,%7},{%8,%9},{%0,%1,%2,%3};"
        : "+f"(c[0]), "+f"(c[1]), "+f"(c[2]), "+f"(c[3])
        : "r"(a0), "r"(a1), "r"(a2), "r"(a3), "r"(b0), "r"(b1));
}
__device__ __forceinline__ void mma_tf32(float c[4],
                                         uint32_t a0, uint32_t a1, uint32_t a2, uint32_t a3,
                                         uint32_t b0, uint32_t b1) {
    asm volatile(
        "mma.sync.aligned.m16n8k8.row.col.f32.tf32.tf32.f32 "
        "{%0,%1,%2,%3},{%4,%5,%6,%7},{%8,%9},{%0,%1,%2,%3};"
        : "+f"(c[0]), "+f"(c[1]), "+f"(c[2]), "+f"(c[3])
        : "r"(a0), "r"(a1), "r"(a2), "r"(a3), "r"(b0), "r"(b1));
}

// ---------------- RMSNorm (fp32 in, fp16 out) ----------------
__global__ void rmsnorm_kernel(const float* __restrict__ x,
                               const float* __restrict__ g,
                               __half* __restrict__ out) {
    int row = blockIdx.x;
    int t = threadIdx.x;
    float4 v = ((const float4*)(x + (size_t)row * DD))[t];
    float s = v.x*v.x + v.y*v.y + v.z*v.z + v.w*v.w;
    #pragma unroll
    for (int o = 16; o; o >>= 1) s += __shfl_xor_sync(0xffffffffu, s, o);
    __shared__ float ws[8];
    __shared__ float tot;
    if ((t & 31) == 0) ws[t >> 5] = s;
    __syncthreads();
    if (t == 0) {
        float z = 0.f;
        #pragma unroll
        for (int i = 0; i < 8; i++) z += ws[i];
        tot = rsqrtf(z * (1.0f / DD) + EPSV);
    }
    __syncthreads();
    float rn = tot;
    float4 gv = ((const float4*)g)[t];
    __half2* op = (__half2*)(out + (size_t)row * DD) + t * 2;
    op[0] = __floats2half2_rn(v.x*rn*gv.x, v.y*rn*gv.y);
    op[1] = __floats2half2_rn(v.z*rn*gv.z, v.w*rn*gv.w);
}

// ---------------- weight convert (fp32 -> fp16) ----------------
__global__ void cvt_h(const float* __restrict__ src, __half* __restrict__ dst, int n4) {
    int i = blockIdx.x * blockDim.x + threadIdx.x;
    int stride = gridDim.x * blockDim.x;
    for (; i < n4; i += stride) {
        float4 v = ((const float4*)src)[i];
        ((__half2*)dst)[i*2]   = __floats2half2_rn(v.x, v.y);
        ((__half2*)dst)[i*2+1] = __floats2half2_rn(v.z, v.w);
    }
}

// ---------------- fp16 mma GEMM: C[M,N] = A[M,K]*B[N,K]^T (+epilogue) ----------------
// 128x128 CTA tile, 256 threads (2Mx4N warps, warp 64x32), m16n8k16, ldmatrix.x4.
// 4-stage cp.async, k-slab 32 halfs, smem row = 64B data + 16B pad (80B pitch).
#define GS      4
#define KSLAB   32
#define PITCHB  80
#define STAGE_B (128*PITCHB)        // 10240 B per matrix per stage
#define PAIR_B  (2*STAGE_B)         // 20480 B
#define GSMEM   (GS*PAIR_B)         // 81920 B

// EPI: 0 = fp16 out, 1 = fp32 out + fp32 residual, 2 = fp16 out gelu
template<int EPI>
__global__ void __launch_bounds__(256, 2)
gemm_h(const __half* __restrict__ A, const __half* __restrict__ B,
       const float* __restrict__ R, void* __restrict__ Cout,
       int M, int N, int K) {
    extern __shared__ __align__(16) char smp[];
    uint32_t sb = smem_u32(smp);
    int tid = threadIdx.x;
    int wid = tid >> 5, lane = tid & 31;
    int warp_m = (wid & 1) * 64;
    int warp_n = (wid >> 1) * 32;
    int tg = lane >> 2, tq = lane & 3;
    int bm = blockIdx.y * 128, bn = blockIdx.x * 128;

    // ldmatrix lane address components
    int li = lane & 7, ls = lane >> 3;
    uint32_t aoffs = (uint32_t)((warp_m + li + (ls & 1) * 8) * PITCHB + (ls >> 1) * 16);
    uint32_t boffs = (uint32_t)((warp_n + li + (ls >> 1) * 8) * PITCHB + (ls & 1) * 16);

    // cp.async loader map: thread -> rows (tid>>2, +64), 16B chunk (tid&3)
    int rA = tid >> 2;
    int ch = tid & 3;
    const __half* Ap = A + (size_t)(bm + rA) * K + ch * 8;
    const __half* Bp = B + (size_t)(bn + rA) * K + ch * 8;
    uint32_t soff = (uint32_t)(rA * PITCHB + ch * 16);
    const uint32_t rowHop = 64u * PITCHB;

    float acc[4][4][4];
    #pragma unroll
    for (int i = 0; i < 4; i++)
        #pragma unroll
        for (int j = 0; j < 4; j++)
            #pragma unroll
            for (int q = 0; q < 4; q++) acc[i][j][q] = 0.f;

    int NS = K / KSLAB;

    #pragma unroll
    for (int p = 0; p < GS - 1; p++) {
        uint32_t da = sb + p * PAIR_B + soff;
        uint32_t db = da + STAGE_B;
        cp16(da,          Ap + p * KSLAB);
        cp16(da + rowHop, Ap + (size_t)64 * K + p * KSLAB);
        cp16(db,          Bp + p * KSLAB);
        cp16(db + rowHop, Bp + (size_t)64 * K + p * KSLAB);
        CP_COMMIT();
    }

    for (int slab = 0; slab < NS; slab++) {
        asm volatile("cp.async.wait_group %0;" :: "n"(GS - 2) : "memory");
        __syncthreads();

        int t = slab + GS - 1;
        if (t < NS) {
            uint32_t da = sb + (t % GS) * PAIR_B + soff;
            uint32_t db = da + STAGE_B;
            cp16(da,          Ap + t * KSLAB);
            cp16(da + rowHop, Ap + (size_t)64 * K + t * KSLAB);
            cp16(db,          Bp + t * KSLAB);
            cp16(db + rowHop, Bp + (size_t)64 * K + t * KSLAB);
        }
        CP_COMMIT();

        uint32_t Asm = sb + (slab % GS) * PAIR_B;
        uint32_t Bsm = Asm + STAGE_B;
        #pragma unroll
        for (int kt = 0; kt < 2; kt++) {
            uint32_t af[4][4];
            #pragma unroll
            for (int mt = 0; mt < 4; mt++)
                ldsm4(af[mt][0], af[mt][1], af[mt][2], af[mt][3],
                      Asm + aoffs + mt * (16 * PITCHB) + kt * 32);
            uint32_t bf[4][2];
            #pragma unroll
            for (int p = 0; p < 2; p++) {
                uint32_t r0, r1, r2, r3;
                ldsm4(r0, r1, r2, r3,
                      Bsm + boffs + p * (16 * PITCHB) + kt * 32);
                bf[p*2][0]   = r0; bf[p*2][1]   = r1;
                bf[p*2+1][0] = r2; bf[p*2+1][1] = r3;
            }
            #pragma unroll
            for (int mt = 0; mt < 4; mt++)
                #pragma unroll
                for (int nt = 0; nt < 4; nt++)
                    mma_f16(acc[mt][nt], af[mt][0], af[mt][1], af[mt][2], af[mt][3],
                            bf[nt][0], bf[nt][1]);
        }
    }

    // epilogue
    #pragma unroll
    for (int mt = 0; mt < 4; mt++) {
        #pragma unroll
        for (int nt = 0; nt < 4; nt++) {
            int r0o = bm + warp_m + mt * 16 + tg;
            int r1o = r0o + 8;
            int c = bn + warp_n + nt * 8 + tq * 2;
            float2 v0 = make_float2(acc[mt][nt][0], acc[mt][nt][1]);
            float2 v1 = make_float2(acc[mt][nt][2], acc[mt][nt][3]);
            if (EPI == 1) {
                float* Cf = (float*)Cout;
                float2 rv0 = *(const float2*)(R + (size_t)r0o * N + c);
                float2 rv1 = *(const float2*)(R + (size_t)r1o * N + c);
                v0.x += rv0.x; v0.y += rv0.y;
                v1.x += rv1.x; v1.y += rv1.y;
                *(float2*)(Cf + (size_t)r0o * N + c) = v0;
                *(float2*)(Cf + (size_t)r1o * N + c) = v1;
            } else {
                if (EPI == 2) {
                    v0.x = gelu_erf(v0.x); v0.y = gelu_erf(v0.y);
                    v1.x = gelu_erf(v1.x); v1.y = gelu_erf(v1.y);
                }
                __half* Ch = (__half*)Cout;
                *(__half2*)(Ch + (size_t)r0o * N + c) = __floats2half2_rn(v0.x, v0.y);
                *(__half2*)(Ch + (size_t)r1o * N + c) = __floats2half2_rn(v1.x, v1.y);
            }
        }
    }
}

// ---------------- flash attention (fp16 in/out, tf32 mma core, causal, dk=64) ----------------
#define FQP 68
#define FSM (3*64*FQP*4)

__global__ void __launch_bounds__(128)
flash_tc(const __half* __restrict__ q, const __half* __restrict__ k,
         const __half* __restrict__ v, __half* __restrict__ o, int ldq) {
    extern __shared__ float smf[];
    float (*Qs)[FQP] = (float(*)[FQP])(smf);
    float (*Ks)[FQP] = (float(*)[FQP])(smf + 64*FQP);
    float (*Vt)[FQP] = (float(*)[FQP])(smf + 2*64*FQP);

    int qi = blockIdx.x;
    int bh = blockIdx.y;
    int b = bh >> 4, h = bh & 15;
    const __half* qp    = q + ((size_t)(b*SS + qi*64)) * ldq + h*DKH;
    const __half* kbase = k + (size_t)b * SS * ldq + h*DKH;
    const __half* vbase = v + (size_t)b * SS * ldq + h*DKH;

    int tid = threadIdx.x;
    int w = tid >> 5, lane = tid & 31;
    int tg = lane >> 2, tq = lane & 3;

    #pragma unroll
    for (int i = 0; i < 8; i++) {
        int f = tid + i * 128;
        int r = f >> 4, c = (f & 15) * 4;
        const __half2* qh = (const __half2*)(qp + (size_t)r * ldq + c);
        float2 f0 = __half22float2(qh[0]);
        float2 f1 = __half22float2(qh[1]);
        Qs[r][c+0] = f0.x * 0.125f;   // exact: fp16 value * 2^-3
        Qs[r][c+1] = f0.y * 0.125f;
        Qs[r][c+2] = f1.x * 0.125f;
        Qs[r][c+3] = f1.y * 0.125f;
    }

    float ofrag[8][4];
    #pragma unroll
    for (int nt = 0; nt < 8; nt++)
        #pragma unroll
        for (int j = 0; j < 4; j++) ofrag[nt][j] = 0.f;
    float mrow0 = -INFINITY, mrow1 = -INFINITY, lrow0 = 0.f, lrow1 = 0.f;

    for (int jt = 0; jt <= qi; jt++) {
        __syncthreads();
        #pragma unroll
        for (int i = 0; i < 8; i++) {
            int f = tid + i * 128;
            int r = f >> 4, c = (f & 15) * 4;
            const __half2* kh = (const __half2*)(kbase + (size_t)(jt*64 + r) * ldq + c);
            float2 k0 = __half22float2(kh[0]);
            float2 k1 = __half22float2(kh[1]);
            Ks[r][c+0] = k0.x; Ks[r][c+1] = k0.y;
            Ks[r][c+2] = k1.x; Ks[r][c+3] = k1.y;
            const __half2* vh = (const __half2*)(vbase + (size_t)(jt*64 + r) * ldq + c);
            float2 v0 = __half22float2(vh[0]);
            float2 v1 = __half22float2(vh[1]);
            Vt[c+0][r] = v0.x; Vt[c+1][r] = v0.y;
            Vt[c+2][r] = v1.x; Vt[c+3][r] = v1.y;
        }
        __syncthreads();

        float s[8][4];
        #pragma unroll
        for (int nt = 0; nt < 8; nt++)
            #pragma unroll
            for (int j = 0; j < 4; j++) s[nt][j] = 0.f;
        #pragma unroll
        for (int kb8 = 0; kb8 < 8; kb8++) {
            int kb = kb8 * 8;
            int r = w * 16;
            uint32_t a0 = __float_as_uint(Qs[r + tg][kb + tq]);
            uint32_t a1 = __float_as_uint(Qs[r + tg + 8][kb + tq]);
            uint32_t a2 = __float_as_uint(Qs[r + tg][kb + tq + 4]);
            uint32_t a3 = __float_as_uint(Qs[r + tg + 8][kb + tq + 4]);
            #pragma unroll
            for (int nt = 0; nt < 8; nt++) {
                uint32_t b0 = __float_as_uint(Ks[nt*8 + tg][kb + tq]);
                uint32_t b1 = __float_as_uint(Ks[nt*8 + tg][kb + tq + 4]);
                mma_tf32(s[nt], a0, a1, a2, a3, b0, b1);
            }
        }

        if (jt == qi) {
            int r0 = w*16 + tg, r1 = r0 + 8;
            #pragma unroll
            for (int nt = 0; nt < 8; nt++) {
                int c0 = nt*8 + 2*tq, c1 = c0 + 1;
                if (c0 > r0) s[nt][0] = -INFINITY;
                if (c1 > r0) s[nt][1] = -INFINITY;
                if (c0 > r1) s[nt][2] = -INFINITY;
                if (c1 > r1) s[nt][3] = -INFINITY;
            }
        }

        float m0 = -INFINITY, m1 = -INFINITY;
        #pragma unroll
        for (int nt = 0; nt < 8; nt++) {
            m0 = fmaxf(m0, fmaxf(s[nt][0], s[nt][1]));
            m1 = fmaxf(m1, fmaxf(s[nt][2], s[nt][3]));
        }
        m0 = fmaxf(m0, __shfl_xor_sync(0xffffffffu, m0, 1));
        m0 = fmaxf(m0, __shfl_xor_sync(0xffffffffu, m0, 2));
        m1 = fmaxf(m1, __shfl_xor_sync(0xffffffffu, m1, 1));
        m1 = fmaxf(m1, __shfl_xor_sync(0xffffffffu, m1, 2));

        float mn0 = fmaxf(mrow0, m0), mn1 = fmaxf(mrow1, m1);
        float corr0 = __expf(mrow0 - mn0), corr1 = __expf(mrow1 - mn1);
        mrow0 = mn0; mrow1 = mn1;

        float rs0 = 0.f, rs1 = 0.f;
        uint32_t pu[8][4];
        #pragma unroll
        for (int nt = 0; nt < 8; nt++) {
            float p0 = __expf(s[nt][0] - mn0);
            float p1 = __expf(s[nt][1] - mn0);
            float p2 = __expf(s[nt][2] - mn1);
            float p3 = __expf(s[nt][3] - mn1);
            rs0 += p0 + p1; rs1 += p2 + p3;
            pu[nt][0] = __float_as_uint(to_tf32(p0));
            pu[nt][1] = __float_as_uint(to_tf32(p1));
            pu[nt][2] = __float_as_uint(to_tf32(p2));
            pu[nt][3] = __float_as_uint(to_tf32(p3));
            ofrag[nt][0] *= corr0; ofrag[nt][1] *= corr0;
            ofrag[nt][2] *= corr1; ofrag[nt][3] *= corr1;
        }
        rs0 += __shfl_xor_sync(0xffffffffu, rs0, 1);
        rs0 += __shfl_xor_sync(0xffffffffu, rs0, 2);
        rs1 += __shfl_xor_sync(0xffffffffu, rs1, 1);
        rs1 += __shfl_xor_sync(0xffffffffu, rs1, 2);
        lrow0 = lrow0 * corr0 + rs0;
        lrow1 = lrow1 * corr1 + rs1;

        int srcl = (lane & 0x1c) | (tq >> 1);
        #pragma unroll
        for (int kt = 0; kt < 8; kt++) {
            uint32_t u00 = __shfl_sync(0xffffffffu, pu[kt][0], srcl);
            uint32_t u01 = __shfl_sync(0xffffffffu, pu[kt][1], srcl);
            uint32_t u10 = __shfl_sync(0xffffffffu, pu[kt][2], srcl);
            uint32_t u11 = __shfl_sync(0xffffffffu, pu[kt][3], srcl);
            uint32_t u20 = __shfl_sync(0xffffffffu, pu[kt][0], srcl + 2);
            uint32_t u21 = __shfl_sync(0xffffffffu, pu[kt][1], srcl + 2);
            uint32_t u30 = __shfl_sync(0xffffffffu, pu[kt][2], srcl + 2);
            uint32_t u31 = __shfl_sync(0xffffffffu, pu[kt][3], srcl + 2);
            bool odd = (tq & 1);
            uint32_t a0 = odd ? u01 : u00;
            uint32_t a1 = odd ? u11 : u10;
            uint32_t a2 = odd ? u21 : u20;
            uint32_t a3 = odd ? u31 : u30;
            int kb = kt * 8;
            #pragma unroll
            for (int nt = 0; nt < 8; nt++) {
                uint32_t b0 = __float_as_uint(Vt[nt*8 + tg][kb + tq]);
                uint32_t b1 = __float_as_uint(Vt[nt*8 + tg][kb + tq + 4]);
                mma_tf32(ofrag[nt], a0, a1, a2, a3, b0, b1);
            }
        }
    }

    float inv0 = 1.0f / lrow0, inv1 = 1.0f / lrow1;
    int r0 = qi*64 + w*16 + tg, r1 = r0 + 8;
    __half* op = o + (size_t)(b*SS) * DD + h*DKH;
    #pragma unroll
    for (int nt = 0; nt < 8; nt++) {
        int c = nt*8 + 2*tq;
        *(__half2*)(op + (size_t)r0 * DD + c) =
            __floats2half2_rn(ofrag[nt][0]*inv0, ofrag[nt][1]*inv0);
        *(__half2*)(op + (size_t)r1 * DD + c) =
            __floats2half2_rn(ofrag[nt][2]*inv1, ofrag[nt][3]*inv1);
    }
}

// ---------------- launch ----------------
extern "C" void kernel_launch(void* const* d_in, const int* in_sizes, int n_in,
                              void* d_out, int out_size) {
    const float* x  = (const float*)d_in[0];
    const float* g1 = (const float*)d_in[1];
    const float* g2 = (const float*)d_in[2];
    const float* wq = (const float*)d_in[3];
    const float* wk = (const float*)d_in[4];
    const float* wv = (const float*)d_in[5];
    const float* wo = (const float*)d_in[6];
    const float* w1 = (const float*)d_in[7];
    const float* w2 = (const float*)d_in[8];
    float* out = (float*)d_out;

    __half *xn, *qkv, *att, *xn2, *ff, *wqkvc, *woc, *w1c, *w2c;
    float* x1;
    cudaGetSymbolAddress((void**)&xn,    g_xn);
    cudaGetSymbolAddress((void**)&qkv,   g_qkv);
    cudaGetSymbolAddress((void**)&att,   g_att);
    cudaGetSymbolAddress((void**)&x1,    g_x1);
    cudaGetSymbolAddress((void**)&xn2,   g_xn2);
    cudaGetSymbolAddress((void**)&ff,    g_ff);
    cudaGetSymbolAddress((void**)&wqkvc, g_wqkv);
    cudaGetSymbolAddress((void**)&woc,   g_woc);
    cudaGetSymbolAddress((void**)&w1c,   g_w1c);
    cudaGetSymbolAddress((void**)&w2c,   g_w2c);

    cudaFuncSetAttribute(flash_tc,
                         cudaFuncAttributeMaxDynamicSharedMemorySize, FSM);
    cudaFuncSetAttribute(gemm_h<0>,
                         cudaFuncAttributeMaxDynamicSharedMemorySize, GSMEM);
    cudaFuncSetAttribute(gemm_h<1>,
                         cudaFuncAttributeMaxDynamicSharedMemorySize, GSMEM);
    cudaFuncSetAttribute(gemm_h<2>,
                         cudaFuncAttributeMaxDynamicSharedMemorySize, GSMEM);

    // weight conversion fp32 -> fp16
    cvt_h<<<256, 256>>>(wq, wqkvc,            DD*DD/4);
    cvt_h<<<256, 256>>>(wk, wqkvc + DD*DD,    DD*DD/4);
    cvt_h<<<256, 256>>>(wv, wqkvc + 2*DD*DD,  DD*DD/4);
    cvt_h<<<256, 256>>>(wo, woc,              DD*DD/4);
    cvt_h<<<512, 256>>>(w1, w1c,              DFF*DD/4);
    cvt_h<<<512, 256>>>(w2, w2c,              DD*DFF/4);

    // 1. xn = rmsnorm(x, g1)  (fp16 out)
    rmsnorm_kernel<<<MM, 256>>>(x, g1, xn);
    // 2. fused QKV: qkv[M,3072] = xn @ [wq;wk;wv]^T  (fp16 out)
    gemm_h<0><<<dim3(3*DD/128, MM/128), 256, GSMEM>>>(xn, wqkvc, nullptr, qkv,
                                                      MM, 3*DD, DD);
    // 3. causal flash attention (fp16 in/out, strided qkv)
    flash_tc<<<dim3(SS/64, BB*HH), 128, FSM>>>(qkv, qkv + DD, qkv + 2*DD, att, 3*DD);
    // 4. x1 = x + att @ wo^T  (fp32 out)
    gemm_h<1><<<dim3(DD/128, MM/128), 256, GSMEM>>>(att, woc, x, x1, MM, DD, DD);
    // 5. xn2 = rmsnorm(x1, g2)  (fp16 out)
    rmsnorm_kernel<<<MM, 256>>>(x1, g2, xn2);
    // 6. ff = gelu(xn2 @ w1^T)  (fp16 out)
    gemm_h<2><<<dim3(DFF/128, MM/128), 256, GSMEM>>>(xn2, w1c, nullptr, ff,
                                                     MM, DFF, DD);
    // 7. out = x1 + ff @ w2^T  (fp32 out)
    gemm_h<1><<<dim3(DD/128, MM/128), 256, GSMEM>>>(ff, w2c, x1, out, MM, DD, DFF);
}

// round 11
// speedup vs baseline: 7.2262x; 1.3577x over previous
#include <cuda_runtime.h>
#include <cuda_fp16.h>
#include <math.h>
#include <stdint.h>

#define BB   2
#define SS   2048
#define DD   1024
#define HH   16
#define DKH  64
#define DFF  4096
#define MM   (BB*SS)     // 4096 rows total
#define EPSV 1e-5f

// ---------------- scratch (device globals: allocation-free) ----------------
__device__ __half g_xn  [MM*DD];
__device__ __half g_qkv [MM*3*DD];   // fused QKV output [M, 3072]
__device__ __half g_att [MM*DD];
__device__ float  g_x1  [MM*DD];     // residual carrier stays fp32
__device__ __half g_xn2 [MM*DD];
__device__ __half g_ff  [MM*DFF];
__device__ __half g_wqkv[3*DD*DD];
__device__ __half g_woc [DD*DD];
__device__ __half g_w1c [DFF*DD];
__device__ __half g_w2c [DD*DFF];

// ---------------- small helpers ----------------
__device__ __forceinline__ float gelu_erf(float x) {
    return 0.5f * x * (1.0f + erff(x * 0.70710678118654752f));
}
__device__ __forceinline__ uint32_t pack_h2(float lo, float hi) {
    uint32_t r;
    asm("{ .reg .f16 l, h;\n\t"
        "cvt.rn.f16.f32 l, %1;\n\t"
        "cvt.rn.f16.f32 h, %2;\n\t"
        "mov.b32 %0, {l, h}; }"
        : "=r"(r) : "f"(lo), "f"(hi));
    return r;
}
__device__ __forceinline__ uint32_t smem_u32(const void* p) {
    uint32_t a;
    asm("{ .reg .u64 t; cvta.to.shared.u64 t, %1; cvt.u32.u64 %0, t; }"
        : "=r"(a) : "l"(p));
    return a;
}
__device__ __forceinline__ void cp16(uint32_t smaddr, const void* gptr) {
    asm volatile("cp.async.cg.shared.global [%0], [%1], 16;"
                 :: "r"(smaddr), "l"(gptr) : "memory");
}
#define CP_COMMIT() asm volatile("cp.async.commit_group;" ::: "memory")

__device__ __forceinline__ void ldsm4(uint32_t& r0, uint32_t& r1,
                                      uint32_t& r2, uint32_t& r3, uint32_t a) {
    asm volatile("ldmatrix.sync.aligned.m8n8.x4.shared.b16 {%0,%1,%2,%3}, [%4];"
                 : "=r"(r0), "=r"(r1), "=r"(r2), "=r"(r3) : "r"(a));
}
__device__ __forceinline__ void ldsm4t(uint32_t& r0, uint32_t& r1,
                                       uint32_t& r2, uint32_t& r3, uint32_t a) {
    asm volatile("ldmatrix.sync.aligned.m8n8.x4.trans.shared.b16 {%0,%1,%2,%3}, [%4];"
                 : "=r"(r0), "=r"(r1), "=r"(r2), "=r"(r3) : "r"(a));
}
__device__ __forceinline__ void mma_f16(float c[4],
                                        uint32_t a0, uint32_t a1, uint32_t a2, uint32_t a3,
                                        uint32_t b0, uint32_t b1) {
    asm volatile(
        "mma.sync.aligned.m16n8k16.row.col.f32.f16.f16.f32 "
        "{%0,%1,%2,%3},{%4,%5,%6,%7},{%8,%9},{%0,%1,%2,%3};"
        : "+f"(c[0]), "+f"(c[1]), "+f"(c[2]), "+f"(c[3])
        : "r"(a0), "r"(a1), "r"(a2), "r"(a3), "r"(b0), "r"(b1));
}

// ---------------- RMSNorm (fp32 in, fp16 out) ----------------
__global__ void rmsnorm_kernel(const float* __restrict__ x,
                               const float* __restrict__ g,
                               __half* __restrict__ out) {
    int row = blockIdx.x;
    int t = threadIdx.x;
    float4 v = ((const float4*)(x + (size_t)row * DD))[t];
    float s = v.x*v.x + v.y*v.y + v.z*v.z + v.w*v.w;
    #pragma unroll
    for (int o = 16; o; o >>= 1) s += __shfl_xor_sync(0xffffffffu, s, o);
    __shared__ float ws[8];
    __shared__ float tot;
    if ((t & 31) == 0) ws[t >> 5] = s;
    __syncthreads();
    if (t == 0) {
        float z = 0.f;
        #pragma unroll
        for (int i = 0; i < 8; i++) z += ws[i];
        tot = rsqrtf(z * (1.0f / DD) + EPSV);
    }
    __syncthreads();
    float rn = tot;
    float4 gv = ((const float4*)g)[t];
    uint32_t* op = (uint32_t*)(out + (size_t)row * DD) + t * 2;
    op[0] = pack_h2(v.x*rn*gv.x, v.y*rn*gv.y);
    op[1] = pack_h2(v.z*rn*gv.z, v.w*rn*gv.w);
}

// ---------------- all weights fp32 -> fp16 in one kernel ----------------
#define W_QKV (3*DD*DD/4)
#define W_O   (DD*DD/4)
#define W_1   (DFF*DD/4)
#define W_2   (DD*DFF/4)
__global__ void cvt_all(const float* __restrict__ wq, const float* __restrict__ wk,
                        const float* __restrict__ wv, const float* __restrict__ wo,
                        const float* __restrict__ w1, const float* __restrict__ w2,
                        __half* __restrict__ dqkv, __half* __restrict__ dwo,
                        __half* __restrict__ dw1, __half* __restrict__ dw2) {
    int total = W_QKV + W_O + W_1 + W_2;
    for (int i = blockIdx.x * blockDim.x + threadIdx.x; i < total;
         i += gridDim.x * blockDim.x) {
        const float* src; __half* dst; int j = i;
        if (j < W_QKV) {
            int seg = j / (DD*DD/4), off = j % (DD*DD/4);
            src = (seg == 0 ? wq : seg == 1 ? wk : wv) + (size_t)off * 4;
            dst = dqkv + (size_t)j * 4;
        } else if ((j -= W_QKV) < W_O) {
            src = wo + (size_t)j * 4; dst = dwo + (size_t)j * 4;
        } else if ((j -= W_O) < W_1) {
            src = w1 + (size_t)j * 4; dst = dw1 + (size_t)j * 4;
        } else {
            j -= W_1;
            src = w2 + (size_t)j * 4; dst = dw2 + (size_t)j * 4;
        }
        float4 v = *(const float4*)src;
        ((uint32_t*)dst)[0] = pack_h2(v.x, v.y);
        ((uint32_t*)dst)[1] = pack_h2(v.z, v.w);
    }
}

// ---------------- fp16 mma GEMM: C[M,N] = A[M,K]*B[N,K]^T (+epilogue) ----------------
#define GS      4
#define KSLAB   32
#define PITCHB  80
#define STAGE_B (128*PITCHB)
#define PAIR_B  (2*STAGE_B)
#define GSMEM   (GS*PAIR_B)

// EPI: 0 = fp16 out, 1 = fp32 out + fp32 residual, 2 = fp16 out gelu
template<int EPI>
__global__ void __launch_bounds__(256, 2)
gemm_h(const __half* __restrict__ A, const __half* __restrict__ B,
       const float* __restrict__ R, void* __restrict__ Cout,
       int M, int N, int K) {
    extern __shared__ __align__(16) char smp[];
    uint32_t sb = smem_u32(smp);
    int tid = threadIdx.x;
    int wid = tid >> 5, lane = tid & 31;
    int warp_m = (wid & 1) * 64;
    int warp_n = (wid >> 1) * 32;
    int tg = lane >> 2, tq = lane & 3;
    int bm = blockIdx.y * 128, bn = blockIdx.x * 128;

    int li = lane & 7, ls = lane >> 3;
    uint32_t aoffs = (uint32_t)((warp_m + li + (ls & 1) * 8) * PITCHB + (ls >> 1) * 16);
    uint32_t boffs = (uint32_t)((warp_n + li + (ls >> 1) * 8) * PITCHB + (ls & 1) * 16);

    int rA = tid >> 2;
    int ch = tid & 3;
    const __half* Ap = A + (size_t)(bm + rA) * K + ch * 8;
    const __half* Bp = B + (size_t)(bn + rA) * K + ch * 8;
    uint32_t soff = (uint32_t)(rA * PITCHB + ch * 16);
    const uint32_t rowHop = 64u * PITCHB;

    float acc[4][4][4];
    #pragma unroll
    for (int i = 0; i < 4; i++)
        #pragma unroll
        for (int j = 0; j < 4; j++)
            #pragma unroll
            for (int q = 0; q < 4; q++) acc[i][j][q] = 0.f;

    int NS = K / KSLAB;

    #pragma unroll
    for (int p = 0; p < GS - 1; p++) {
        uint32_t da = sb + p * PAIR_B + soff;
        uint32_t db = da + STAGE_B;
        cp16(da,          Ap + p * KSLAB);
        cp16(da + rowHop, Ap + (size_t)64 * K + p * KSLAB);
        cp16(db,          Bp + p * KSLAB);
        cp16(db + rowHop, Bp + (size_t)64 * K + p * KSLAB);
        CP_COMMIT();
    }

    for (int slab = 0; slab < NS; slab++) {
        asm volatile("cp.async.wait_group %0;" :: "n"(GS - 2) : "memory");
        __syncthreads();

        int t = slab + GS - 1;
        if (t < NS) {
            uint32_t da = sb + (t % GS) * PAIR_B + soff;
            uint32_t db = da + STAGE_B;
            cp16(da,          Ap + t * KSLAB);
            cp16(da + rowHop, Ap + (size_t)64 * K + t * KSLAB);
            cp16(db,          Bp + t * KSLAB);
            cp16(db + rowHop, Bp + (size_t)64 * K + t * KSLAB);
        }
        CP_COMMIT();

        uint32_t Asm = sb + (slab % GS) * PAIR_B;
        uint32_t Bsm = Asm + STAGE_B;
        #pragma unroll
        for (int kt = 0; kt < 2; kt++) {
            uint32_t af[4][4];
            #pragma unroll
            for (int mt = 0; mt < 4; mt++)
                ldsm4(af[mt][0], af[mt][1], af[mt][2], af[mt][3],
                      Asm + aoffs + mt * (16 * PITCHB) + kt * 32);
            uint32_t bf[4][2];
            #pragma unroll
            for (int p = 0; p < 2; p++) {
                uint32_t r0, r1, r2, r3;
                ldsm4(r0, r1, r2, r3,
                      Bsm + boffs + p * (16 * PITCHB) + kt * 32);
                bf[p*2][0]   = r0; bf[p*2][1]   = r1;
                bf[p*2+1][0] = r2; bf[p*2+1][1] = r3;
            }
            #pragma unroll
            for (int mt = 0; mt < 4; mt++)
                #pragma unroll
                for (int nt = 0; nt < 4; nt++)
                    mma_f16(acc[mt][nt], af[mt][0], af[mt][1], af[mt][2], af[mt][3],
                            bf[nt][0], bf[nt][1]);
        }
    }

    #pragma unroll
    for (int mt = 0; mt < 4; mt++) {
        #pragma unroll
        for (int nt = 0; nt < 4; nt++) {
            int r0o = bm + warp_m + mt * 16 + tg;
            int r1o = r0o + 8;
            int c = bn + warp_n + nt * 8 + tq * 2;
            float2 v0 = make_float2(acc[mt][nt][0], acc[mt][nt][1]);
            float2 v1 = make_float2(acc[mt][nt][2], acc[mt][nt][3]);
            if (EPI == 1) {
                float* Cf = (float*)Cout;
                float2 rv0 = *(const float2*)(R + (size_t)r0o * N + c);
                float2 rv1 = *(const float2*)(R + (size_t)r1o * N + c);
                v0.x += rv0.x; v0.y += rv0.y;
                v1.x += rv1.x; v1.y += rv1.y;
                *(float2*)(Cf + (size_t)r0o * N + c) = v0;
                *(float2*)(Cf + (size_t)r1o * N + c) = v1;
            } else {
                if (EPI == 2) {
                    v0.x = gelu_erf(v0.x); v0.y = gelu_erf(v0.y);
                    v1.x = gelu_erf(v1.x); v1.y = gelu_erf(v1.y);
                }
                __half* Ch = (__half*)Cout;
                *(uint32_t*)(Ch + (size_t)r0o * N + c) = pack_h2(v0.x, v0.y);
                *(uint32_t*)(Ch + (size_t)r1o * N + c) = pack_h2(v1.x, v1.y);
            }
        }
    }
}

// ---------------- fp16 flash attention (causal, dk=64, m16n8k16 + ldmatrix) ----------------
// 128 threads = 4 warps; warp w owns q-rows [w*16, w*16+16).
// smem: Qh, Kh, Vh each 64 rows x 72-half pitch (144B), row-major; data cols 0-63.
#define FPH   72
#define FPHB  (FPH*2)
#define FSMH  (3*64*FPHB)   // 27648 B

__global__ void __launch_bounds__(128)
flash_h(const __half* __restrict__ q, const __half* __restrict__ k,
        const __half* __restrict__ v, __half* __restrict__ o, int ldq) {
    extern __shared__ __align__(16) char smc[];
    uint32_t sbase = smem_u32(smc);
    __half* Qh = (__half*)smc;
    __half* Kh = Qh + 64*FPH;
    __half* Vh = Kh + 64*FPH;
    uint32_t Ksm = sbase + 64*FPHB;
    uint32_t Vsm = sbase + 2*64*FPHB;

    int qi = blockIdx.x;
    int bh = blockIdx.y;
    int b = bh >> 4, h = bh & 15;
    const __half* qp    = q + ((size_t)(b*SS + qi*64)) * ldq + h*DKH;
    const __half* kbase = k + (size_t)b * SS * ldq + h*DKH;
    const __half* vbase = v + (size_t)b * SS * ldq + h*DKH;

    int tid = threadIdx.x;
    int w = tid >> 5, lane = tid & 31;
    int tg = lane >> 2, tq = lane & 3;
    int li = lane & 7, ls = lane >> 3;

    // loader map (128 threads): rows {lr, lr+32} x chunks {lch, lch+4} (16B chunks, 8/row)
    int lr = tid >> 2, lch = tid & 3;

    uint32_t aoffs = (uint32_t)((w*16 + li + (ls & 1) * 8) * FPHB + (ls >> 1) * 16);
    uint32_t boffs = (uint32_t)((li + (ls >> 1) * 8) * FPHB + (ls & 1) * 16);  // K frags
    uint32_t voffs = (uint32_t)((li + (ls & 1) * 8) * FPHB + (ls >> 1) * 16);  // V trans frags

    // Load Q tile (scale by 0.125, exact in fp16): 2 rows x 2 chunks per thread
    {
        __half2 sc = __floats2half2_rn(0.125f, 0.125f);
        #pragma unroll
        for (int i = 0; i < 2; i++) {
            int r = lr + i * 32;
            #pragma unroll
            for (int jc = 0; jc < 2; jc++) {
                int c = (lch + jc * 4) * 8;
                const __half2* qg = (const __half2*)(qp + (size_t)r * ldq + c);
                __half2* qs = (__half2*)(Qh + r * FPH + c);
                #pragma unroll
                for (int j = 0; j < 4; j++) qs[j] = __hmul2(qg[j], sc);
            }
        }
    }
    __syncthreads();
    uint32_t qf[4][4];
    #pragma unroll
    for (int kt = 0; kt < 4; kt++)
        ldsm4(qf[kt][0], qf[kt][1], qf[kt][2], qf[kt][3], sbase + aoffs + kt * 32);

    float ofrag[8][4];
    #pragma unroll
    for (int nt = 0; nt < 8; nt++)
        #pragma unroll
        for (int j = 0; j < 4; j++) ofrag[nt][j] = 0.f;
    float mrow0 = -INFINITY, mrow1 = -INFINITY, lrow0 = 0.f, lrow1 = 0.f;

    for (int jt = 0; jt <= qi; jt++) {
        __syncthreads();   // prior tile's frag reads done before overwrite
        #pragma unroll
        for (int i = 0; i < 2; i++) {
            int r = lr + i * 32;
            #pragma unroll
            for (int jc = 0; jc < 2; jc++) {
                int c = (lch + jc * 4) * 8;
                const uint4* kg = (const uint4*)(kbase + (size_t)(jt*64 + r) * ldq + c);
                const uint4* vg = (const uint4*)(vbase + (size_t)(jt*64 + r) * ldq + c);
                *(uint4*)(Kh + r * FPH + c) = *kg;
                *(uint4*)(Vh + r * FPH + c) = *vg;
            }
        }
        __syncthreads();

        // S = Q K^T : 4 k-steps x 8 n-tiles
        float s[8][4];
        #pragma unroll
        for (int nt = 0; nt < 8; nt++)
            #pragma unroll
            for (int j = 0; j < 4; j++) s[nt][j] = 0.f;
        #pragma unroll
        for (int kt = 0; kt < 4; kt++) {
            #pragma unroll
            for (int nb = 0; nb < 4; nb++) {
                uint32_t r0, r1, r2, r3;
                ldsm4(r0, r1, r2, r3, Ksm + boffs + nb * (16 * FPHB) + kt * 32);
                mma_f16(s[nb*2],   qf[kt][0], qf[kt][1], qf[kt][2], qf[kt][3], r0, r1);
                mma_f16(s[nb*2+1], qf[kt][0], qf[kt][1], qf[kt][2], qf[kt][3], r2, r3);
            }
        }

        // causal mask on diagonal tile
        if (jt == qi) {
            int r0 = w*16 + tg, r1 = r0 + 8;
            #pragma unroll
            for (int nt = 0; nt < 8; nt++) {
                int c0 = nt*8 + 2*tq, c1 = c0 + 1;
                if (c0 > r0) s[nt][0] = -INFINITY;
                if (c1 > r0) s[nt][1] = -INFINITY;
                if (c0 > r1) s[nt][2] = -INFINITY;
                if (c1 > r1) s[nt][3] = -INFINITY;
            }
        }

        // online softmax (quad reductions)
        float m0 = -INFINITY, m1 = -INFINITY;
        #pragma unroll
        for (int nt = 0; nt < 8; nt++) {
            m0 = fmaxf(m0, fmaxf(s[nt][0], s[nt][1]));
            m1 = fmaxf(m1, fmaxf(s[nt][2], s[nt][3]));
        }
        m0 = fmaxf(m0, __shfl_xor_sync(0xffffffffu, m0, 1));
        m0 = fmaxf(m0, __shfl_xor_sync(0xffffffffu, m0, 2));
        m1 = fmaxf(m1, __shfl_xor_sync(0xffffffffu, m1, 1));
        m1 = fmaxf(m1, __shfl_xor_sync(0xffffffffu, m1, 2));

        float mn0 = fmaxf(mrow0, m0), mn1 = fmaxf(mrow1, m1);
        float corr0 = __expf(mrow0 - mn0), corr1 = __expf(mrow1 - mn1);
        mrow0 = mn0; mrow1 = mn1;

        float rs0 = 0.f, rs1 = 0.f;
        uint32_t pk[4][4];   // A-fragments of P for PV (C->A identity, no shuffles)
        #pragma unroll
        for (int nt = 0; nt < 8; nt++) {
            float p0 = __expf(s[nt][0] - mn0);
            float p1 = __expf(s[nt][1] - mn0);
            float p2 = __expf(s[nt][2] - mn1);
            float p3 = __expf(s[nt][3] - mn1);
            rs0 += p0 + p1; rs1 += p2 + p3;
            int kt = nt >> 1, hi = nt & 1;
            pk[kt][hi*2]     = pack_h2(p0, p1);
            pk[kt][hi*2 + 1] = pack_h2(p2, p3);
            ofrag[nt][0] *= corr0; ofrag[nt][1] *= corr0;
            ofrag[nt][2] *= corr1; ofrag[nt][3] *= corr1;
        }
        rs0 += __shfl_xor_sync(0xffffffffu, rs0, 1);
        rs0 += __shfl_xor_sync(0xffffffffu, rs0, 2);
        rs1 += __shfl_xor_sync(0xffffffffu, rs1, 1);
        rs1 += __shfl_xor_sync(0xffffffffu, rs1, 2);
        lrow0 = lrow0 * corr0 + rs0;
        lrow1 = lrow1 * corr1 + rs1;

        // O += P V : B frags via ldmatrix.trans of row-major V
        #pragma unroll
        for (int kt = 0; kt < 4; kt++) {
            #pragma unroll
            for (int nb = 0; nb < 4; nb++) {
                uint32_t r0, r1, r2, r3;
                ldsm4t(r0, r1, r2, r3,
                       Vsm + voffs + kt * (16 * FPHB) + nb * 32);
                mma_f16(ofrag[nb*2],   pk[kt][0], pk[kt][1], pk[kt][2], pk[kt][3], r0, r1);
                mma_f16(ofrag[nb*2+1], pk[kt][0], pk[kt][1], pk[kt][2], pk[kt][3], r2, r3);
            }
        }
    }

    float inv0 = 1.0f / lrow0, inv1 = 1.0f / lrow1;
    int r0 = qi*64 + w*16 + tg, r1 = r0 + 8;
    __half* op = o + (size_t)(b*SS) * DD + h*DKH;
    #pragma unroll
    for (int nt = 0; nt < 8; nt++) {
        int c = nt*8 + 2*tq;
        *(uint32_t*)(op + (size_t)r0 * DD + c) =
            pack_h2(ofrag[nt][0]*inv0, ofrag[nt][1]*inv0);
        *(uint32_t*)(op + (size_t)r1 * DD + c) =
            pack_h2(ofrag[nt][2]*inv1, ofrag[nt][3]*inv1);
    }
}

// ---------------- launch ----------------
extern "C" void kernel_launch(void* const* d_in, const int* in_sizes, int n_in,
                              void* d_out, int out_size) {
    const float* x  = (const float*)d_in[0];
    const float* g1 = (const float*)d_in[1];
    const float* g2 = (const float*)d_in[2];
    const float* wq = (const float*)d_in[3];
    const float* wk = (const float*)d_in[4];
    const float* wv = (const float*)d_in[5];
    const float* wo = (const float*)d_in[6];
    const float* w1 = (const float*)d_in[7];
    const float* w2 = (const float*)d_in[8];
    float* out = (float*)d_out;

    __half *xn, *qkv, *att, *xn2, *ff, *wqkvc, *woc, *w1c, *w2c;
    float* x1;
    cudaGetSymbolAddress((void**)&xn,    g_xn);
    cudaGetSymbolAddress((void**)&qkv,   g_qkv);
    cudaGetSymbolAddress((void**)&att,   g_att);
    cudaGetSymbolAddress((void**)&x1,    g_x1);
    cudaGetSymbolAddress((void**)&xn2,   g_xn2);
    cudaGetSymbolAddress((void**)&ff,    g_ff);
    cudaGetSymbolAddress((void**)&wqkvc, g_wqkv);
    cudaGetSymbolAddress((void**)&woc,   g_woc);
    cudaGetSymbolAddress((void**)&w1c,   g_w1c);
    cudaGetSymbolAddress((void**)&w2c,   g_w2c);

    cudaFuncSetAttribute(flash_h,
                         cudaFuncAttributeMaxDynamicSharedMemorySize, FSMH);
    cudaFuncSetAttribute(gemm_h<0>,
                         cudaFuncAttributeMaxDynamicSharedMemorySize, GSMEM);
    cudaFuncSetAttribute(gemm_h<1>,
                         cudaFuncAttributeMaxDynamicSharedMemorySize, GSMEM);
    cudaFuncSetAttribute(gemm_h<2>,
                         cudaFuncAttributeMaxDynamicSharedMemorySize, GSMEM);

    // all weight conversions in one launch
    cvt_all<<<1024, 256>>>(wq, wk, wv, wo, w1, w2, wqkvc, woc, w1c, w2c);

    // 1. xn = rmsnorm(x, g1)  (fp16 out)
    rmsnorm_kernel<<<MM, 256>>>(x, g1, xn);
    // 2. fused QKV: qkv[M,3072] = xn @ [wq;wk;wv]^T  (fp16 out)
    gemm_h<0><<<dim3(3*DD/128, MM/128), 256, GSMEM>>>(xn, wqkvc, nullptr, qkv,
                                                      MM, 3*DD, DD);
    // 3. causal flash attention (fp16 mma, strided qkv)
    flash_h<<<dim3(SS/64, BB*HH), 128, FSMH>>>(qkv, qkv + DD, qkv + 2*DD, att, 3*DD);
    // 4. x1 = x + att @ wo^T  (fp32 out)
    gemm_h<1><<<dim3(DD/128, MM/128), 256, GSMEM>>>(att, woc, x, x1, MM, DD, DD);
    // 5. xn2 = rmsnorm(x1, g2)  (fp16 out)
    rmsnorm_kernel<<<MM, 256>>>(x1, g2, xn2);
    // 6. ff = gelu(xn2 @ w1^T)  (fp16 out)
    gemm_h<2><<<dim3(DFF/128, MM/128), 256, GSMEM>>>(xn2, w1c, nullptr, ff,
                                                     MM, DFF, DD);
    // 7. out = x1 + ff @ w2^T  (fp32 out)
    gemm_h<1><<<dim3(DD/128, MM/128), 256, GSMEM>>>(ff, w2c, x1, out, MM, DD, DFF);
}

// round 12
// speedup vs baseline: 7.5273x; 1.0417x over previous
#include <cuda_runtime.h>
#include <cuda_fp16.h>
#include <math.h>
#include <stdint.h>

#define BB   2
#define SS   2048
#define DD   1024
#define HH   16
#define DKH  64
#define DFF  4096
#define MM   (BB*SS)     // 4096 rows total
#define EPSV 1e-5f

// ---------------- scratch (device globals: allocation-free) ----------------
__device__ __half g_xn  [MM*DD];
__device__ __half g_qkv [MM*3*DD];
__device__ __half g_att [MM*DD];
__device__ float  g_x1  [MM*DD];
__device__ __half g_xn2 [MM*DD];
__device__ __half g_ff  [MM*DFF];
__device__ __half g_wqkv[3*DD*DD];
__device__ __half g_woc [DD*DD];
__device__ __half g_w1c [DFF*DD];
__device__ __half g_w2c [DD*DFF];

// ---------------- small helpers ----------------
__device__ __forceinline__ float gelu_erf(float x) {
    return 0.5f * x * (1.0f + erff(x * 0.70710678118654752f));
}
__device__ __forceinline__ uint32_t pack_h2(float lo, float hi) {
    uint32_t r;
    asm("{ .reg .f16 l, h;\n\t"
        "cvt.rn.f16.f32 l, %1;\n\t"
        "cvt.rn.f16.f32 h, %2;\n\t"
        "mov.b32 %0, {l, h}; }"
        : "=r"(r) : "f"(lo), "f"(hi));
    return r;
}
__device__ __forceinline__ uint32_t ex2_h2(uint32_t x) {
    uint32_t r;
    asm("ex2.approx.f16x2 %0, %1;" : "=r"(r) : "r"(x));
    return r;
}
__device__ __forceinline__ float ex2f(float x) {
    float r;
    asm("ex2.approx.ftz.f32 %0, %1;" : "=f"(r) : "f"(x));
    return r;
}
__device__ __forceinline__ uint32_t smem_u32(const void* p) {
    uint32_t a;
    asm("{ .reg .u64 t; cvta.to.shared.u64 t, %1; cvt.u32.u64 %0, t; }"
        : "=r"(a) : "l"(p));
    return a;
}
__device__ __forceinline__ void cp16(uint32_t smaddr, const void* gptr) {
    asm volatile("cp.async.cg.shared.global [%0], [%1], 16;"
                 :: "r"(smaddr), "l"(gptr) : "memory");
}
#define CP_COMMIT() asm volatile("cp.async.commit_group;" ::: "memory")

__device__ __forceinline__ void ldsm4(uint32_t& r0, uint32_t& r1,
                                      uint32_t& r2, uint32_t& r3, uint32_t a) {
    asm volatile("ldmatrix.sync.aligned.m8n8.x4.shared.b16 {%0,%1,%2,%3}, [%4];"
                 : "=r"(r0), "=r"(r1), "=r"(r2), "=r"(r3) : "r"(a));
}
__device__ __forceinline__ void ldsm4t(uint32_t& r0, uint32_t& r1,
                                       uint32_t& r2, uint32_t& r3, uint32_t a) {
    asm volatile("ldmatrix.sync.aligned.m8n8.x4.trans.shared.b16 {%0,%1,%2,%3}, [%4];"
                 : "=r"(r0), "=r"(r1), "=r"(r2), "=r"(r3) : "r"(a));
}
__device__ __forceinline__ void mma_f16(float c[4],
                                        uint32_t a0, uint32_t a1, uint32_t a2, uint32_t a3,
                                        uint32_t b0, uint32_t b1) {
    asm volatile(
        "mma.sync.aligned.m16n8k16.row.col.f32.f16.f16.f32 "
        "{%0,%1,%2,%3},{%4,%5,%6,%7},{%8,%9},{%0,%1,%2,%3};"
        : "+f"(c[0]), "+f"(c[1]), "+f"(c[2]), "+f"(c[3])
        : "r"(a0), "r"(a1), "r"(a2), "r"(a3), "r"(b0), "r"(b1));
}

// ---------------- RMSNorm (fp32 in, fp16 out) ----------------
__global__ void rmsnorm_kernel(const float* __restrict__ x,
                               const float* __restrict__ g,
                               __half* __restrict__ out) {
    int row = blockIdx.x;
    int t = threadIdx.x;
    float4 v = ((const float4*)(x + (size_t)row * DD))[t];
    float s = v.x*v.x + v.y*v.y + v.z*v.z + v.w*v.w;
    #pragma unroll
    for (int o = 16; o; o >>= 1) s += __shfl_xor_sync(0xffffffffu, s, o);
    __shared__ float ws[8];
    __shared__ float tot;
    if ((t & 31) == 0) ws[t >> 5] = s;
    __syncthreads();
    if (t == 0) {
        float z = 0.f;
        #pragma unroll
        for (int i = 0; i < 8; i++) z += ws[i];
        tot = rsqrtf(z * (1.0f / DD) + EPSV);
    }
    __syncthreads();
    float rn = tot;
    float4 gv = ((const float4*)g)[t];
    uint32_t* op = (uint32_t*)(out + (size_t)row * DD) + t * 2;
    op[0] = pack_h2(v.x*rn*gv.x, v.y*rn*gv.y);
    op[1] = pack_h2(v.z*rn*gv.z, v.w*rn*gv.w);
}

// ---------------- all weights fp32 -> fp16 in one kernel ----------------
#define W_QKV (3*DD*DD/4)
#define W_O   (DD*DD/4)
#define W_1   (DFF*DD/4)
#define W_2   (DD*DFF/4)
__global__ void cvt_all(const float* __restrict__ wq, const float* __restrict__ wk,
                        const float* __restrict__ wv, const float* __restrict__ wo,
                        const float* __restrict__ w1, const float* __restrict__ w2,
                        __half* __restrict__ dqkv, __half* __restrict__ dwo,
                        __half* __restrict__ dw1, __half* __restrict__ dw2) {
    int total = W_QKV + W_O + W_1 + W_2;
    for (int i = blockIdx.x * blockDim.x + threadIdx.x; i < total;
         i += gridDim.x * blockDim.x) {
        const float* src; __half* dst; int j = i;
        if (j < W_QKV) {
            int seg = j / (DD*DD/4), off = j % (DD*DD/4);
            src = (seg == 0 ? wq : seg == 1 ? wk : wv) + (size_t)off * 4;
            dst = dqkv + (size_t)j * 4;
        } else if ((j -= W_QKV) < W_O) {
            src = wo + (size_t)j * 4; dst = dwo + (size_t)j * 4;
        } else if ((j -= W_O) < W_1) {
            src = w1 + (size_t)j * 4; dst = dw1 + (size_t)j * 4;
        } else {
            j -= W_1;
            src = w2 + (size_t)j * 4; dst = dw2 + (size_t)j * 4;
        }
        float4 v = *(const float4*)src;
        ((uint32_t*)dst)[0] = pack_h2(v.x, v.y);
        ((uint32_t*)dst)[1] = pack_h2(v.z, v.w);
    }
}

// ---------------- fp16 mma GEMM: C[M,N] = A[M,K]*B[N,K]^T (+epilogue) ----------------
// 128x128 tile, 256 thr (2Mx4N warps, warp 64x32), k-slab 64, GS=3 cp.async stages.
// slab row = 64 halfs = 128B data + 16B pad -> 144B pitch (8-row ldsm conflict-free).
#define GS      3
#define KSLAB   64
#define PITCHB  144
#define STAGE_B (128*PITCHB)        // 18432 B
#define PAIR_B  (2*STAGE_B)         // 36864 B
#define GSMEM   (GS*PAIR_B)         // 110592 B

// EPI: 0 = fp16 out, 1 = fp32 out + fp32 residual, 2 = fp16 out gelu
template<int EPI>
__global__ void __launch_bounds__(256, 2)
gemm_h(const __half* __restrict__ A, const __half* __restrict__ B,
       const float* __restrict__ R, void* __restrict__ Cout,
       int M, int N, int K) {
    extern __shared__ __align__(16) char smp[];
    uint32_t sb = smem_u32(smp);
    int tid = threadIdx.x;
    int wid = tid >> 5, lane = tid & 31;
    int warp_m = (wid & 1) * 64;
    int warp_n = (wid >> 1) * 32;
    int tg = lane >> 2, tq = lane & 3;
    int bm = blockIdx.y * 128, bn = blockIdx.x * 128;

    int li = lane & 7, ls = lane >> 3;
    uint32_t aoffs = (uint32_t)((warp_m + li + (ls & 1) * 8) * PITCHB + (ls >> 1) * 16);
    uint32_t boffs = (uint32_t)((warp_n + li + (ls >> 1) * 8) * PITCHB + (ls & 1) * 16);

    // loader map: 128 rows x 8 chunks (16B); thread covers 4 (row,chunk) pairs
    int lrow[4], lchn[4];
    #pragma unroll
    for (int p = 0; p < 4; p++) {
        int idx = tid + p * 256;
        lrow[p] = idx >> 3;
        lchn[p] = idx & 7;
    }

    float acc[4][4][4];
    #pragma unroll
    for (int i = 0; i < 4; i++)
        #pragma unroll
        for (int j = 0; j < 4; j++)
            #pragma unroll
            for (int q = 0; q < 4; q++) acc[i][j][q] = 0.f;

    int NS = K / KSLAB;

    #pragma unroll
    for (int p = 0; p < GS - 1; p++) {
        uint32_t sa = sb + p * PAIR_B;
        uint32_t sbb = sa + STAGE_B;
        #pragma unroll
        for (int i = 0; i < 4; i++) {
            cp16(sa  + lrow[i]*PITCHB + lchn[i]*16,
                 A + (size_t)(bm + lrow[i]) * K + p * KSLAB + lchn[i]*8);
            cp16(sbb + lrow[i]*PITCHB + lchn[i]*16,
                 B + (size_t)(bn + lrow[i]) * K + p * KSLAB + lchn[i]*8);
        }
        CP_COMMIT();
    }

    for (int slab = 0; slab < NS; slab++) {
        asm volatile("cp.async.wait_group %0;" :: "n"(GS - 2) : "memory");
        __syncthreads();

        int t = slab + GS - 1;
        if (t < NS) {
            uint32_t sa = sb + (t % GS) * PAIR_B;
            uint32_t sbb = sa + STAGE_B;
            #pragma unroll
            for (int i = 0; i < 4; i++) {
                cp16(sa  + lrow[i]*PITCHB + lchn[i]*16,
                     A + (size_t)(bm + lrow[i]) * K + t * KSLAB + lchn[i]*8);
                cp16(sbb + lrow[i]*PITCHB + lchn[i]*16,
                     B + (size_t)(bn + lrow[i]) * K + t * KSLAB + lchn[i]*8);
            }
        }
        CP_COMMIT();

        uint32_t Asm = sb + (slab % GS) * PAIR_B;
        uint32_t Bsm = Asm + STAGE_B;
        #pragma unroll
        for (int kt = 0; kt < 4; kt++) {
            uint32_t af[4][4];
            #pragma unroll
            for (int mt = 0; mt < 4; mt++)
                ldsm4(af[mt][0], af[mt][1], af[mt][2], af[mt][3],
                      Asm + aoffs + mt * (16 * PITCHB) + kt * 32);
            uint32_t bf[4][2];
            #pragma unroll
            for (int p = 0; p < 2; p++) {
                uint32_t r0, r1, r2, r3;
                ldsm4(r0, r1, r2, r3,
                      Bsm + boffs + p * (16 * PITCHB) + kt * 32);
                bf[p*2][0]   = r0; bf[p*2][1]   = r1;
                bf[p*2+1][0] = r2; bf[p*2+1][1] = r3;
            }
            #pragma unroll
            for (int mt = 0; mt < 4; mt++)
                #pragma unroll
                for (int nt = 0; nt < 4; nt++)
                    mma_f16(acc[mt][nt], af[mt][0], af[mt][1], af[mt][2], af[mt][3],
                            bf[nt][0], bf[nt][1]);
        }
    }

    #pragma unroll
    for (int mt = 0; mt < 4; mt++) {
        #pragma unroll
        for (int nt = 0; nt < 4; nt++) {
            int r0o = bm + warp_m + mt * 16 + tg;
            int r1o = r0o + 8;
            int c = bn + warp_n + nt * 8 + tq * 2;
            float2 v0 = make_float2(acc[mt][nt][0], acc[mt][nt][1]);
            float2 v1 = make_float2(acc[mt][nt][2], acc[mt][nt][3]);
            if (EPI == 1) {
                float* Cf = (float*)Cout;
                float2 rv0 = *(const float2*)(R + (size_t)r0o * N + c);
                float2 rv1 = *(const float2*)(R + (size_t)r1o * N + c);
                v0.x += rv0.x; v0.y += rv0.y;
                v1.x += rv1.x; v1.y += rv1.y;
                *(float2*)(Cf + (size_t)r0o * N + c) = v0;
                *(float2*)(Cf + (size_t)r1o * N + c) = v1;
            } else {
                if (EPI == 2) {
                    v0.x = gelu_erf(v0.x); v0.y = gelu_erf(v0.y);
                    v1.x = gelu_erf(v1.x); v1.y = gelu_erf(v1.y);
                }
                __half* Ch = (__half*)Cout;
                *(uint32_t*)(Ch + (size_t)r0o * N + c) = pack_h2(v0.x, v0.y);
                *(uint32_t*)(Ch + (size_t)r1o * N + c) = pack_h2(v1.x, v1.y);
            }
        }
    }
}

// ---------------- fp16 flash attention (causal, dk=64, log2-softmax, cp.async) ----------------
// 128 thr = 4 warps, warp w owns q-rows [w*16, w*16+16).
// smem: Q (64x144B) + 2 stages of {K,V} (each 64x144B). Total 46080 B.
#define FPH   72
#define FPHB  (FPH*2)           // 144
#define QBYTES (64*FPHB)        // 9216
#define KVPAIR (2*QBYTES)       // 18432 per stage
#define FSMH  (QBYTES + 2*KVPAIR)   // 46080
#define QSCAL 0.18033688011112042f  // 0.125 * log2(e)

__global__ void __launch_bounds__(128)
flash_h(const __half* __restrict__ q, const __half* __restrict__ k,
        const __half* __restrict__ v, __half* __restrict__ o, int ldq) {
    extern __shared__ __align__(16) char smc[];
    uint32_t sbase = smem_u32(smc);
    __half* Qh = (__half*)smc;

    int qi = blockIdx.x;
    int bh = blockIdx.y;
    int b = bh >> 4, h = bh & 15;
    const __half* qp    = q + ((size_t)(b*SS + qi*64)) * ldq + h*DKH;
    const __half* kbase = k + (size_t)b * SS * ldq + h*DKH;
    const __half* vbase = v + (size_t)b * SS * ldq + h*DKH;

    int tid = threadIdx.x;
    int w = tid >> 5, lane = tid & 31;
    int tg = lane >> 2, tq = lane & 3;
    int li = lane & 7, ls = lane >> 3;

    // loader map: rows {lr, lr+32} x chunks {lch, lch+4} (8 chunks of 16B per row)
    int lr = tid >> 2, lch = tid & 3;

    uint32_t aoffs = (uint32_t)((w*16 + li + (ls & 1) * 8) * FPHB + (ls >> 1) * 16);
    uint32_t boffs = (uint32_t)((li + (ls >> 1) * 8) * FPHB + (ls & 1) * 16);
    uint32_t voffs = (uint32_t)((li + (ls & 1) * 8) * FPHB + (ls >> 1) * 16);

    // Load Q (scale 0.125*log2e in f32, repack fp16)
    #pragma unroll
    for (int i = 0; i < 2; i++) {
        int r = lr + i * 32;
        #pragma unroll
        for (int jc = 0; jc < 2; jc++) {
            int c = (lch + jc * 4) * 8;
            const __half2* qg = (const __half2*)(qp + (size_t)r * ldq + c);
            uint32_t* qs = (uint32_t*)(Qh + r * FPH + c);
            #pragma unroll
            for (int j = 0; j < 4; j++) {
                float2 f = __half22float2(qg[j]);
                qs[j] = pack_h2(f.x * QSCAL, f.y * QSCAL);
            }
        }
    }
    __syncthreads();
    uint32_t qf[4][4];
    #pragma unroll
    for (int kt = 0; kt < 4; kt++)
        ldsm4(qf[kt][0], qf[kt][1], qf[kt][2], qf[kt][3], sbase + aoffs + kt * 32);

    // prologue: tile 0 K/V into stage 0
    {
        uint32_t Ks0 = sbase + QBYTES;
        uint32_t Vs0 = Ks0 + QBYTES;
        #pragma unroll
        for (int i = 0; i < 2; i++) {
            int r = lr + i * 32;
            #pragma unroll
            for (int jc = 0; jc < 2; jc++) {
                int c = lch + jc * 4;
                cp16(Ks0 + r*FPHB + c*16, kbase + (size_t)r * ldq + c*8);
                cp16(Vs0 + r*FPHB + c*16, vbase + (size_t)r * ldq + c*8);
            }
        }
        CP_COMMIT();
    }

    float ofrag[8][4];
    #pragma unroll
    for (int nt = 0; nt < 8; nt++)
        #pragma unroll
        for (int j = 0; j < 4; j++) ofrag[nt][j] = 0.f;
    float mrow0 = -INFINITY, mrow1 = -INFINITY, lrow0 = 0.f, lrow1 = 0.f;
    const uint32_t ONE2 = 0x3C003C00u;

    for (int jt = 0; jt <= qi; jt++) {
        __syncthreads();   // all warps done reading the stage we're about to overwrite
        if (jt < qi) {
            int nt_ = jt + 1;
            uint32_t Ksn = sbase + QBYTES + ((nt_) & 1) * KVPAIR;
            uint32_t Vsn = Ksn + QBYTES;
            #pragma unroll
            for (int i = 0; i < 2; i++) {
                int r = lr + i * 32;
                #pragma unroll
                for (int jc = 0; jc < 2; jc++) {
                    int c = lch + jc * 4;
                    cp16(Ksn + r*FPHB + c*16, kbase + (size_t)(nt_*64 + r) * ldq + c*8);
                    cp16(Vsn + r*FPHB + c*16, vbase + (size_t)(nt_*64 + r) * ldq + c*8);
                }
            }
            CP_COMMIT();
            asm volatile("cp.async.wait_group 1;" ::: "memory");
        } else {
            asm volatile("cp.async.wait_group 0;" ::: "memory");
        }
        __syncthreads();   // tile jt data visible

        uint32_t Ksm = sbase + QBYTES + (jt & 1) * KVPAIR;
        uint32_t Vsm = Ksm + QBYTES;

        // S = Q K^T (log2 domain)
        float s[8][4];
        #pragma unroll
        for (int nt = 0; nt < 8; nt++)
            #pragma unroll
            for (int j = 0; j < 4; j++) s[nt][j] = 0.f;
        #pragma unroll
        for (int kt = 0; kt < 4; kt++) {
            #pragma unroll
            for (int nb = 0; nb < 4; nb++) {
                uint32_t r0, r1, r2, r3;
                ldsm4(r0, r1, r2, r3, Ksm + boffs + nb * (16 * FPHB) + kt * 32);
                mma_f16(s[nb*2],   qf[kt][0], qf[kt][1], qf[kt][2], qf[kt][3], r0, r1);
                mma_f16(s[nb*2+1], qf[kt][0], qf[kt][1], qf[kt][2], qf[kt][3], r2, r3);
            }
        }

        if (jt == qi) {
            int r0 = w*16 + tg, r1 = r0 + 8;
            #pragma unroll
            for (int nt = 0; nt < 8; nt++) {
                int c0 = nt*8 + 2*tq, c1 = c0 + 1;
                if (c0 > r0) s[nt][0] = -INFINITY;
                if (c1 > r0) s[nt][1] = -INFINITY;
                if (c0 > r1) s[nt][2] = -INFINITY;
                if (c1 > r1) s[nt][3] = -INFINITY;
            }
        }

        float m0 = -INFINITY, m1 = -INFINITY;
        #pragma unroll
        for (int nt = 0; nt < 8; nt++) {
            m0 = fmaxf(m0, fmaxf(s[nt][0], s[nt][1]));
            m1 = fmaxf(m1, fmaxf(s[nt][2], s[nt][3]));
        }
        m0 = fmaxf(m0, __shfl_xor_sync(0xffffffffu, m0, 1));
        m0 = fmaxf(m0, __shfl_xor_sync(0xffffffffu, m0, 2));
        m1 = fmaxf(m1, __shfl_xor_sync(0xffffffffu, m1, 1));
        m1 = fmaxf(m1, __shfl_xor_sync(0xffffffffu, m1, 2));

        float mn0 = fmaxf(mrow0, m0), mn1 = fmaxf(mrow1, m1);
        float corr0 = ex2f(mrow0 - mn0), corr1 = ex2f(mrow1 - mn1);
        mrow0 = mn0; mrow1 = mn1;

        // p = 2^(s - mn) via fp16x2 ex2; pk are PV A-fragments (C->A identity)
        uint32_t pk[4][4];
        #pragma unroll
        for (int nt = 0; nt < 8; nt++) {
            int kt = nt >> 1, hi = nt & 1;
            pk[kt][hi*2]     = ex2_h2(pack_h2(s[nt][0] - mn0, s[nt][1] - mn0));
            pk[kt][hi*2 + 1] = ex2_h2(pack_h2(s[nt][2] - mn1, s[nt][3] - mn1));
            ofrag[nt][0] *= corr0; ofrag[nt][1] *= corr0;
            ofrag[nt][2] *= corr1; ofrag[nt][3] *= corr1;
        }

        // row sums via mma against all-ones B fragment (fp32 accumulate)
        float rsf[4] = {0.f, 0.f, 0.f, 0.f};
        #pragma unroll
        for (int kt = 0; kt < 4; kt++)
            mma_f16(rsf, pk[kt][0], pk[kt][1], pk[kt][2], pk[kt][3], ONE2, ONE2);
        lrow0 = lrow0 * corr0 + rsf[0];
        lrow1 = lrow1 * corr1 + rsf[2];

        // O += P V
        #pragma unroll
        for (int kt = 0; kt < 4; kt++) {
            #pragma unroll
            for (int nb = 0; nb < 4; nb++) {
                uint32_t r0, r1, r2, r3;
                ldsm4t(r0, r1, r2, r3,
                       Vsm + voffs + kt * (16 * FPHB) + nb * 32);
                mma_f16(ofrag[nb*2],   pk[kt][0], pk[kt][1], pk[kt][2], pk[kt][3], r0, r1);
                mma_f16(ofrag[nb*2+1], pk[kt][0], pk[kt][1], pk[kt][2], pk[kt][3], r2, r3);
            }
        }
    }

    float inv0 = 1.0f / lrow0, inv1 = 1.0f / lrow1;
    int r0 = qi*64 + w*16 + tg, r1 = r0 + 8;
    __half* op = o + (size_t)(b*SS) * DD + h*DKH;
    #pragma unroll
    for (int nt = 0; nt < 8; nt++) {
        int c = nt*8 + 2*tq;
        *(uint32_t*)(op + (size_t)r0 * DD + c) =
            pack_h2(ofrag[nt][0]*inv0, ofrag[nt][1]*inv0);
        *(uint32_t*)(op + (size_t)r1 * DD + c) =
            pack_h2(ofrag[nt][2]*inv1, ofrag[nt][3]*inv1);
    }
}

// ---------------- launch ----------------
extern "C" void kernel_launch(void* const* d_in, const int* in_sizes, int n_in,
                              void* d_out, int out_size) {
    const float* x  = (const float*)d_in[0];
    const float* g1 = (const float*)d_in[1];
    const float* g2 = (const float*)d_in[2];
    const float* wq = (const float*)d_in[3];
    const float* wk = (const float*)d_in[4];
    const float* wv = (const float*)d_in[5];
    const float* wo = (const float*)d_in[6];
    const float* w1 = (const float*)d_in[7];
    const float* w2 = (const float*)d_in[8];
    float* out = (float*)d_out;

    __half *xn, *qkv, *att, *xn2, *ff, *wqkvc, *woc, *w1c, *w2c;
    float* x1;
    cudaGetSymbolAddress((void**)&xn,    g_xn);
    cudaGetSymbolAddress((void**)&qkv,   g_qkv);
    cudaGetSymbolAddress((void**)&att,   g_att);
    cudaGetSymbolAddress((void**)&x1,    g_x1);
    cudaGetSymbolAddress((void**)&xn2,   g_xn2);
    cudaGetSymbolAddress((void**)&ff,    g_ff);
    cudaGetSymbolAddress((void**)&wqkvc, g_wqkv);
    cudaGetSymbolAddress((void**)&woc,   g_woc);
    cudaGetSymbolAddress((void**)&w1c,   g_w1c);
    cudaGetSymbolAddress((void**)&w2c,   g_w2c);

    cudaFuncSetAttribute(flash_h,
                         cudaFuncAttributeMaxDynamicSharedMemorySize, FSMH);
    cudaFuncSetAttribute(gemm_h<0>,
                         cudaFuncAttributeMaxDynamicSharedMemorySize, GSMEM);
    cudaFuncSetAttribute(gemm_h<1>,
                         cudaFuncAttributeMaxDynamicSharedMemorySize, GSMEM);
    cudaFuncSetAttribute(gemm_h<2>,
                         cudaFuncAttributeMaxDynamicSharedMemorySize, GSMEM);

    cvt_all<<<1024, 256>>>(wq, wk, wv, wo, w1, w2, wqkvc, woc, w1c, w2c);

    // 1. xn = rmsnorm(x, g1)
    rmsnorm_kernel<<<MM, 256>>>(x, g1, xn);
    // 2. fused QKV
    gemm_h<0><<<dim3(3*DD/128, MM/128), 256, GSMEM>>>(xn, wqkvc, nullptr, qkv,
                                                      MM, 3*DD, DD);
    // 3. causal flash attention
    flash_h<<<dim3(SS/64, BB*HH), 128, FSMH>>>(qkv, qkv + DD, qkv + 2*DD, att, 3*DD);
    // 4. x1 = x + att @ wo^T
    gemm_h<1><<<dim3(DD/128, MM/128), 256, GSMEM>>>(att, woc, x, x1, MM, DD, DD);
    // 5. xn2 = rmsnorm(x1, g2)
    rmsnorm_kernel<<<MM, 256>>>(x1, g2, xn2);
    // 6. ff = gelu(xn2 @ w1^T)
    gemm_h<2><<<dim3(DFF/128, MM/128), 256, GSMEM>>>(xn2, w1c, nullptr, ff,
                                                     MM, DFF, DD);
    // 7. out = x1 + ff @ w2^T
    gemm_h<1><<<dim3(DD/128, MM/128), 256, GSMEM>>>(ff, w2c, x1, out, MM, DD, DFF);
}